// round 1
// baseline (speedup 1.0000x reference)
#include <cuda_runtime.h>
#include <math.h>

#define B_    2
#define T_    2048
#define C_    2048
#define HQ_   16
#define HKV_  4
#define DH_   128
#define WIN_  512
#define NQKV_ 3072          // (HQ + 2*HKV) * DH
#define MTOK_ 4096          // B * T

// ---------------- scratch (static __device__, no allocations) ----------------
__device__ float g_qkv[MTOK_ * NQKV_];          // 50.3 MB
__device__ float g_Q[B_ * HQ_ * T_ * DH_];      // 33.5 MB
__device__ float g_K[B_ * HKV_ * T_ * DH_];     //  8.4 MB
__device__ float g_V[B_ * HKV_ * T_ * DH_];     //  8.4 MB
__device__ float g_y[MTOK_ * C_];               // 33.5 MB

// ============================================================================
// GEMM:  C[M,N] = A[M,K] @ B[N,K]^T   (both row-major, K contiguous)
// 128x128 block tile, BK=16, 256 threads, 8x8 per thread (split 4+4 quadrants),
// register-staged prefetch of the next K-tile.
// ============================================================================
__global__ __launch_bounds__(256) void gemm_nt(
    const float* __restrict__ A, const float* __restrict__ Bm,
    float* __restrict__ Cm, int M, int N, int K)
{
    __shared__ __align__(16) float As[16][132];
    __shared__ __align__(16) float Bs[16][132];

    const int tid = threadIdx.x;
    const int tx  = tid & 15;
    const int ty  = tid >> 4;
    const int m0  = blockIdx.y << 7;
    const int n0  = blockIdx.x << 7;

    // load mapping: thread -> (row lr / lr+64, k-cols lc..lc+3)
    const int lr = tid >> 2;           // 0..63
    const int lc = (tid & 3) << 2;     // 0,4,8,12

    const float* Ap = A  + (size_t)(m0 + lr) * K + lc;
    const float* Bp = Bm + (size_t)(n0 + lr) * K + lc;
    const size_t rowK64 = (size_t)64 * K;

    float acc[8][8];
#pragma unroll
    for (int i = 0; i < 8; i++)
#pragma unroll
        for (int j = 0; j < 8; j++) acc[i][j] = 0.f;

    const int KT = K >> 4;

    float4 ra0 = *(const float4*)(Ap);
    float4 ra1 = *(const float4*)(Ap + rowK64);
    float4 rb0 = *(const float4*)(Bp);
    float4 rb1 = *(const float4*)(Bp + rowK64);

    for (int kt = 0; kt < KT; ++kt) {
        // store staged regs -> smem (transposed: As[k][m])
        As[lc+0][lr]    = ra0.x; As[lc+1][lr]    = ra0.y; As[lc+2][lr]    = ra0.z; As[lc+3][lr]    = ra0.w;
        As[lc+0][lr+64] = ra1.x; As[lc+1][lr+64] = ra1.y; As[lc+2][lr+64] = ra1.z; As[lc+3][lr+64] = ra1.w;
        Bs[lc+0][lr]    = rb0.x; Bs[lc+1][lr]    = rb0.y; Bs[lc+2][lr]    = rb0.z; Bs[lc+3][lr]    = rb0.w;
        Bs[lc+0][lr+64] = rb1.x; Bs[lc+1][lr+64] = rb1.y; Bs[lc+2][lr+64] = rb1.z; Bs[lc+3][lr+64] = rb1.w;
        __syncthreads();

        if (kt + 1 < KT) {
            const float* Ap2 = Ap + (size_t)(kt + 1) * 16;
            const float* Bp2 = Bp + (size_t)(kt + 1) * 16;
            ra0 = *(const float4*)(Ap2);
            ra1 = *(const float4*)(Ap2 + rowK64);
            rb0 = *(const float4*)(Bp2);
            rb1 = *(const float4*)(Bp2 + rowK64);
        }

#pragma unroll
        for (int kk = 0; kk < 16; ++kk) {
            float av[8], bv[8];
            float4 a0 = *(const float4*)&As[kk][ty << 2];
            float4 a1 = *(const float4*)&As[kk][64 + (ty << 2)];
            float4 b0 = *(const float4*)&Bs[kk][tx << 2];
            float4 b1 = *(const float4*)&Bs[kk][64 + (tx << 2)];
            av[0]=a0.x; av[1]=a0.y; av[2]=a0.z; av[3]=a0.w;
            av[4]=a1.x; av[5]=a1.y; av[6]=a1.z; av[7]=a1.w;
            bv[0]=b0.x; bv[1]=b0.y; bv[2]=b0.z; bv[3]=b0.w;
            bv[4]=b1.x; bv[5]=b1.y; bv[6]=b1.z; bv[7]=b1.w;
#pragma unroll
            for (int i = 0; i < 8; i++)
#pragma unroll
                for (int j = 0; j < 8; j++)
                    acc[i][j] += av[i] * bv[j];
        }
        __syncthreads();
    }

#pragma unroll
    for (int i = 0; i < 8; i++) {
        const int row = m0 + ((i < 4) ? (ty * 4 + i) : (64 + ty * 4 + (i - 4)));
        float* cp = Cm + (size_t)row * N + n0;
        *(float4*)(cp + (tx << 2))      = make_float4(acc[i][0], acc[i][1], acc[i][2], acc[i][3]);
        *(float4*)(cp + 64 + (tx << 2)) = make_float4(acc[i][4], acc[i][5], acc[i][6], acc[i][7]);
    }
}

// ============================================================================
// RoPE + RMSNorm + head split.  One block per (head, t, b), 64 threads
// (one thread per even/odd pair).  heads 0..15 -> Q, 16..19 -> K, 20..23 -> V.
// ============================================================================
__global__ __launch_bounds__(64) void rope_rms(
    const float* __restrict__ qkv,
    float* __restrict__ Qo, float* __restrict__ Ko, float* __restrict__ Vo)
{
    const int h = blockIdx.x;
    const int t = blockIdx.y;
    const int b = blockIdx.z;
    const int i = threadIdx.x;      // 0..63

    const float* src = qkv + ((size_t)(b * T_ + t)) * NQKV_ + h * DH_;
    float x0 = src[2 * i];
    float x1 = src[2 * i + 1];

    if (h >= HQ_ + HKV_) {          // V heads: plain copy/transpose
        float* dst = Vo + ((size_t)(b * HKV_ + (h - HQ_ - HKV_)) * T_ + t) * DH_;
        dst[2 * i]     = x0;
        dst[2 * i + 1] = x1;
        return;
    }

    // RoPE
    const float inv_freq = powf(10000.0f, -(float)i * (1.0f / 64.0f));
    const float ang = (float)t * inv_freq;
    float sn, cs;
    sincosf(ang, &sn, &cs);
    const float y0 = x0 * cs - x1 * sn;
    const float y1 = x1 * cs + x0 * sn;

    // RMS norm over DH=128
    float ss = y0 * y0 + y1 * y1;
#pragma unroll
    for (int off = 16; off; off >>= 1)
        ss += __shfl_xor_sync(0xffffffffu, ss, off);
    __shared__ float sh[2];
    if ((i & 31) == 0) sh[i >> 5] = ss;
    __syncthreads();
    const float rn = rsqrtf((sh[0] + sh[1]) * (1.0f / 128.0f) + 1.1920929e-07f);

    float* dst = (h < HQ_)
        ? Qo + ((size_t)(b * HQ_ + h) * T_ + t) * DH_
        : Ko + ((size_t)(b * HKV_ + (h - HQ_)) * T_ + t) * DH_;
    dst[2 * i]     = y0 * rn;
    dst[2 * i + 1] = y1 * rn;
}

// ============================================================================
// Sliding-window flash attention.  64 queries x 64 keys per tile, DH=128.
// 256 threads = 16x16, each thread 4 rows x 4 score cols (S) / 4 rows x 8 out
// cols (PV).  Row state (m, l) replicated across the 16 lanes of a row group.
// ============================================================================
#define QS_ 129
#define VS_ 128
#define PS_ 68
#define ATTN_SMEM ((64 * QS_ * 2 + 64 * VS_ + 64 * PS_) * (int)sizeof(float))

__global__ __launch_bounds__(256) void attn_kernel(
    const float* __restrict__ Qg, const float* __restrict__ Kg,
    const float* __restrict__ Vg, float* __restrict__ Yg)
{
    extern __shared__ __align__(16) float sm[];
    float* Qs  = sm;                    // 64 x 129
    float* Ks  = Qs  + 64 * QS_;        // 64 x 129
    float* Vsm = Ks  + 64 * QS_;        // 64 x 128
    float* Psm = Vsm + 64 * VS_;        // 64 x 68

    const int tid = threadIdx.x;
    const int tx  = tid & 15;
    const int ty  = tid >> 4;
    const int q0  = blockIdx.x << 6;
    const int h   = blockIdx.y;
    const int b   = blockIdx.z;
    const int hk  = h >> 2;             // rep = HQ/HKV = 4

    const float* Qp = Qg + ((size_t)(b * HQ_ + h) * T_ + q0) * DH_;
    const float* Kp = Kg + ((size_t)(b * HKV_ + hk) * T_) * DH_;
    const float* Vp = Vg + ((size_t)(b * HKV_ + hk) * T_) * DH_;

    const float qsc = 0.08838834764831845f;  // 1/sqrt(128)
    for (int li = tid; li < 64 * 32; li += 256) {
        const int r  = li >> 5;
        const int c4 = (li & 31) << 2;
        float4 v = *(const float4*)(Qp + (size_t)r * DH_ + c4);
        float* d = Qs + r * QS_ + c4;
        d[0] = v.x * qsc; d[1] = v.y * qsc; d[2] = v.z * qsc; d[3] = v.w * qsc;
    }

    float m_i[4], l_i[4], acc[4][8];
#pragma unroll
    for (int i = 0; i < 4; i++) {
        m_i[i] = -1e30f; l_i[i] = 0.f;
#pragma unroll
        for (int j = 0; j < 8; j++) acc[i][j] = 0.f;
    }

    int lo = q0 - (WIN_ - 1); if (lo < 0) lo = 0;
    const int kt0 = lo >> 6;
    const int kt1 = q0 >> 6;

    const float* qrow0 = Qs + (ty * 4 + 0) * QS_;
    const float* qrow1 = Qs + (ty * 4 + 1) * QS_;
    const float* qrow2 = Qs + (ty * 4 + 2) * QS_;
    const float* qrow3 = Qs + (ty * 4 + 3) * QS_;
    const float* krow0 = Ks + (tx * 4 + 0) * QS_;
    const float* krow1 = Ks + (tx * 4 + 1) * QS_;
    const float* krow2 = Ks + (tx * 4 + 2) * QS_;
    const float* krow3 = Ks + (tx * 4 + 3) * QS_;

    for (int kt = kt0; kt <= kt1; ++kt) {
        const int k0 = kt << 6;

        // load K (transpose-padded) and V tiles
        for (int li = tid; li < 64 * 32; li += 256) {
            const int r  = li >> 5;
            const int c4 = (li & 31) << 2;
            float4 kv = *(const float4*)(Kp + (size_t)(k0 + r) * DH_ + c4);
            float* kd = Ks + r * QS_ + c4;
            kd[0] = kv.x; kd[1] = kv.y; kd[2] = kv.z; kd[3] = kv.w;
            *(float4*)(Vsm + r * VS_ + c4) =
                *(const float4*)(Vp + (size_t)(k0 + r) * DH_ + c4);
        }
        __syncthreads();

        // S = (Q/sqrt(d)) K^T
        float s[4][4];
#pragma unroll
        for (int i = 0; i < 4; i++)
#pragma unroll
            for (int j = 0; j < 4; j++) s[i][j] = 0.f;

#pragma unroll 8
        for (int d = 0; d < DH_; ++d) {
            float qa[4], kb[4];
            qa[0] = qrow0[d]; qa[1] = qrow1[d]; qa[2] = qrow2[d]; qa[3] = qrow3[d];
            kb[0] = krow0[d]; kb[1] = krow1[d]; kb[2] = krow2[d]; kb[3] = krow3[d];
#pragma unroll
            for (int i = 0; i < 4; i++)
#pragma unroll
                for (int j = 0; j < 4; j++)
                    s[i][j] += qa[i] * kb[j];
        }

        // mask + online softmax update, write P tile
#pragma unroll
        for (int i = 0; i < 4; i++) {
            const int qi = q0 + ty * 4 + i;
            float rmax = -1e30f;
#pragma unroll
            for (int j = 0; j < 4; j++) {
                const int kj = k0 + tx * 4 + j;
                const float sv = (qi >= kj && (qi - kj) < WIN_) ? s[i][j] : -1e30f;
                s[i][j] = sv;
                rmax = fmaxf(rmax, sv);
            }
#pragma unroll
            for (int off = 8; off; off >>= 1)
                rmax = fmaxf(rmax, __shfl_xor_sync(0xffffffffu, rmax, off));
            const float mn = fmaxf(m_i[i], rmax);

            float4 pv;
            pv.x = __expf(s[i][0] - mn);
            pv.y = __expf(s[i][1] - mn);
            pv.z = __expf(s[i][2] - mn);
            pv.w = __expf(s[i][3] - mn);
            float rs = pv.x + pv.y + pv.z + pv.w;
#pragma unroll
            for (int off = 8; off; off >>= 1)
                rs += __shfl_xor_sync(0xffffffffu, rs, off);

            const float sc = __expf(m_i[i] - mn);
            l_i[i] = l_i[i] * sc + rs;
            m_i[i] = mn;
#pragma unroll
            for (int j = 0; j < 8; j++) acc[i][j] *= sc;

            *(float4*)(Psm + (ty * 4 + i) * PS_ + (tx << 2)) = pv;
        }
        __syncthreads();

        // acc += P @ V
        const float* pr0 = Psm + (ty * 4 + 0) * PS_;
        const float* pr1 = Psm + (ty * 4 + 1) * PS_;
        const float* pr2 = Psm + (ty * 4 + 2) * PS_;
        const float* pr3 = Psm + (ty * 4 + 3) * PS_;
#pragma unroll 4
        for (int k = 0; k < 64; ++k) {
            float p[4];
            p[0] = pr0[k]; p[1] = pr1[k]; p[2] = pr2[k]; p[3] = pr3[k];
            float4 v0 = *(const float4*)(Vsm + k * VS_ + (tx << 3));
            float4 v1 = *(const float4*)(Vsm + k * VS_ + (tx << 3) + 4);
            float vv[8] = {v0.x, v0.y, v0.z, v0.w, v1.x, v1.y, v1.z, v1.w};
#pragma unroll
            for (int i = 0; i < 4; i++)
#pragma unroll
                for (int j = 0; j < 8; j++)
                    acc[i][j] += p[i] * vv[j];
        }
        __syncthreads();
    }

    // epilogue: y[b][t][h*128 + c] = acc / l
#pragma unroll
    for (int i = 0; i < 4; i++) {
        const float inv = 1.0f / l_i[i];
        const int t = q0 + ty * 4 + i;
        float* yp = Yg + ((size_t)(b * T_ + t)) * C_ + h * DH_ + (tx << 3);
        *(float4*)yp       = make_float4(acc[i][0] * inv, acc[i][1] * inv,
                                         acc[i][2] * inv, acc[i][3] * inv);
        *(float4*)(yp + 4) = make_float4(acc[i][4] * inv, acc[i][5] * inv,
                                         acc[i][6] * inv, acc[i][7] * inv);
    }
}

// ============================================================================
// launch
// ============================================================================
extern "C" void kernel_launch(void* const* d_in, const int* in_sizes, int n_in,
                              void* d_out, int out_size)
{
    const float* x      = (const float*)d_in[0];
    const float* w_qkv  = (const float*)d_in[1];
    const float* w_proj = (const float*)d_in[2];
    float* out = (float*)d_out;

    float *p_qkv, *p_Q, *p_K, *p_V, *p_y;
    cudaGetSymbolAddress((void**)&p_qkv, g_qkv);
    cudaGetSymbolAddress((void**)&p_Q,   g_Q);
    cudaGetSymbolAddress((void**)&p_K,   g_K);
    cudaGetSymbolAddress((void**)&p_V,   g_V);
    cudaGetSymbolAddress((void**)&p_y,   g_y);

    // 1) qkv = x @ w_qkv^T
    gemm_nt<<<dim3(NQKV_ / 128, MTOK_ / 128), 256>>>(x, w_qkv, p_qkv, MTOK_, NQKV_, C_);

    // 2) RoPE + RMSNorm + split into Q/K/V head-major layouts
    rope_rms<<<dim3(HQ_ + 2 * HKV_, T_, B_), 64>>>(p_qkv, p_Q, p_K, p_V);

    // 3) sliding-window attention -> y in (B, T, C) layout
    cudaFuncSetAttribute(attn_kernel, cudaFuncAttributeMaxDynamicSharedMemorySize, ATTN_SMEM);
    attn_kernel<<<dim3(T_ / 64, HQ_, B_), 256, ATTN_SMEM>>>(p_Q, p_K, p_V, p_y);

    // 4) out = y @ w_proj^T
    gemm_nt<<<dim3(C_ / 128, MTOK_ / 128), 256>>>(p_y, w_proj, out, MTOK_, C_, C_);
}

// round 2
// speedup vs baseline: 1.1281x; 1.1281x over previous
#include <cuda_runtime.h>
#include <math.h>
#include <mma.h>

using namespace nvcuda;

#define B_    2
#define T_    2048
#define C_    2048
#define HQ_   16
#define HKV_  4
#define DH_   128
#define WIN_  512
#define NQKV_ 3072          // (HQ + 2*HKV) * DH
#define MTOK_ 4096          // B * T

// ---------------- scratch (static __device__, no allocations) ----------------
__device__ float g_qkv[MTOK_ * NQKV_];          // 50.3 MB
__device__ float g_Q[B_ * HQ_ * T_ * DH_];      // 33.5 MB
__device__ float g_K[B_ * HKV_ * T_ * DH_];     //  8.4 MB
__device__ float g_V[B_ * HKV_ * T_ * DH_];     //  8.4 MB
__device__ float g_y[MTOK_ * C_];               // 33.5 MB

// ============================================================================
// TF32 tensor-core GEMM:  C[M,N] = A[M,K] @ B[N,K]^T  (row-major, K contig)
// 128x128 block tile, BK=32, 256 threads = 8 warps (2m x 4n), each warp a
// 64x32 tile = 4x2 wmma 16x16x8 fragments.  Register-staged global prefetch.
// ============================================================================
#define BM_  128
#define BN_  128
#define BKg_ 32
#define BKP_ 36

__global__ __launch_bounds__(256) void gemm_tf32(
    const float* __restrict__ A, const float* __restrict__ Bm,
    float* __restrict__ Cm, int M, int N, int K)
{
    __shared__ __align__(16) float As[BM_][BKP_];
    __shared__ __align__(16) float Bs[BN_][BKP_];

    const int tid = threadIdx.x;
    const int wid = tid >> 5;
    const int m0  = blockIdx.y * BM_;
    const int n0  = blockIdx.x * BN_;
    const int wm  = (wid & 1) * 64;     // warp m-offset in tile
    const int wn  = (wid >> 1) * 32;    // warp n-offset in tile

    wmma::fragment<wmma::accumulator, 16, 16, 8, float> acc[4][2];
#pragma unroll
    for (int i = 0; i < 4; i++)
#pragma unroll
        for (int j = 0; j < 2; j++)
            wmma::fill_fragment(acc[i][j], 0.0f);

    const int KT = K / BKg_;

    // each thread stages 4 float4 from A and 4 from B per k-tile (coalesced)
    float4 ra[4], rb[4];
#pragma unroll
    for (int q = 0; q < 4; q++) {
        const int idx = tid + 256 * q;
        const int r = idx >> 3;
        const int c = (idx & 7) << 2;
        ra[q] = *(const float4*)(A  + (size_t)(m0 + r) * K + c);
        rb[q] = *(const float4*)(Bm + (size_t)(n0 + r) * K + c);
    }

    for (int kt = 0; kt < KT; ++kt) {
#pragma unroll
        for (int q = 0; q < 4; q++) {
            const int idx = tid + 256 * q;
            const int r = idx >> 3;
            const int c = (idx & 7) << 2;
            As[r][c + 0] = wmma::__float_to_tf32(ra[q].x);
            As[r][c + 1] = wmma::__float_to_tf32(ra[q].y);
            As[r][c + 2] = wmma::__float_to_tf32(ra[q].z);
            As[r][c + 3] = wmma::__float_to_tf32(ra[q].w);
            Bs[r][c + 0] = wmma::__float_to_tf32(rb[q].x);
            Bs[r][c + 1] = wmma::__float_to_tf32(rb[q].y);
            Bs[r][c + 2] = wmma::__float_to_tf32(rb[q].z);
            Bs[r][c + 3] = wmma::__float_to_tf32(rb[q].w);
        }
        __syncthreads();

        if (kt + 1 < KT) {
            const float* Ap = A  + (size_t)(kt + 1) * BKg_;
            const float* Bp = Bm + (size_t)(kt + 1) * BKg_;
#pragma unroll
            for (int q = 0; q < 4; q++) {
                const int idx = tid + 256 * q;
                const int r = idx >> 3;
                const int c = (idx & 7) << 2;
                ra[q] = *(const float4*)(Ap + (size_t)(m0 + r) * K + c);
                rb[q] = *(const float4*)(Bp + (size_t)(n0 + r) * K + c);
            }
        }

#pragma unroll
        for (int ks = 0; ks < 4; ++ks) {
            wmma::fragment<wmma::matrix_a, 16, 16, 8, wmma::precision::tf32, wmma::row_major> af[4];
            wmma::fragment<wmma::matrix_b, 16, 16, 8, wmma::precision::tf32, wmma::col_major> bf[2];
#pragma unroll
            for (int i = 0; i < 4; i++)
                wmma::load_matrix_sync(af[i], &As[wm + i * 16][ks * 8], BKP_);
#pragma unroll
            for (int j = 0; j < 2; j++)
                wmma::load_matrix_sync(bf[j], &Bs[wn + j * 16][ks * 8], BKP_);
#pragma unroll
            for (int i = 0; i < 4; i++)
#pragma unroll
                for (int j = 0; j < 2; j++)
                    wmma::mma_sync(acc[i][j], af[i], bf[j], acc[i][j]);
        }
        __syncthreads();
    }

#pragma unroll
    for (int i = 0; i < 4; i++)
#pragma unroll
        for (int j = 0; j < 2; j++)
            wmma::store_matrix_sync(
                Cm + (size_t)(m0 + wm + i * 16) * N + (n0 + wn + j * 16),
                acc[i][j], N, wmma::mem_row_major);
}

// ============================================================================
// RoPE + RMSNorm + head split.  One block per (head, t, b), 64 threads
// (one thread per even/odd pair).  heads 0..15 -> Q, 16..19 -> K, 20..23 -> V.
// ============================================================================
__global__ __launch_bounds__(64) void rope_rms(
    const float* __restrict__ qkv,
    float* __restrict__ Qo, float* __restrict__ Ko, float* __restrict__ Vo)
{
    const int h = blockIdx.x;
    const int t = blockIdx.y;
    const int b = blockIdx.z;
    const int i = threadIdx.x;      // 0..63

    const float* src = qkv + ((size_t)(b * T_ + t)) * NQKV_ + h * DH_;
    float x0 = src[2 * i];
    float x1 = src[2 * i + 1];

    if (h >= HQ_ + HKV_) {          // V heads: plain copy/transpose
        float* dst = Vo + ((size_t)(b * HKV_ + (h - HQ_ - HKV_)) * T_ + t) * DH_;
        dst[2 * i]     = x0;
        dst[2 * i + 1] = x1;
        return;
    }

    // RoPE
    const float inv_freq = powf(10000.0f, -(float)i * (1.0f / 64.0f));
    const float ang = (float)t * inv_freq;
    float sn, cs;
    sincosf(ang, &sn, &cs);
    const float y0 = x0 * cs - x1 * sn;
    const float y1 = x1 * cs + x0 * sn;

    // RMS norm over DH=128
    float ss = y0 * y0 + y1 * y1;
#pragma unroll
    for (int off = 16; off; off >>= 1)
        ss += __shfl_xor_sync(0xffffffffu, ss, off);
    __shared__ float sh[2];
    if ((i & 31) == 0) sh[i >> 5] = ss;
    __syncthreads();
    const float rn = rsqrtf((sh[0] + sh[1]) * (1.0f / 128.0f) + 1.1920929e-07f);

    float* dst = (h < HQ_)
        ? Qo + ((size_t)(b * HQ_ + h) * T_ + t) * DH_
        : Ko + ((size_t)(b * HKV_ + (h - HQ_)) * T_ + t) * DH_;
    dst[2 * i]     = y0 * rn;
    dst[2 * i + 1] = y1 * rn;
}

// ============================================================================
// Sliding-window flash attention.  64 queries x 64 keys per tile, DH=128.
// 256 threads = 16x16, each thread 4 rows x 4 score cols (S) / 4 rows x 8 out
// cols (PV).  Row state (m, l) replicated across the 16 lanes of a row group.
// ============================================================================
#define QS_ 129
#define VS_ 128
#define PS_ 68
#define ATTN_SMEM ((64 * QS_ * 2 + 64 * VS_ + 64 * PS_) * (int)sizeof(float))

__global__ __launch_bounds__(256) void attn_kernel(
    const float* __restrict__ Qg, const float* __restrict__ Kg,
    const float* __restrict__ Vg, float* __restrict__ Yg)
{
    extern __shared__ __align__(16) float sm[];
    float* Qs  = sm;                    // 64 x 129
    float* Ks  = Qs  + 64 * QS_;        // 64 x 129
    float* Vsm = Ks  + 64 * QS_;        // 64 x 128
    float* Psm = Vsm + 64 * VS_;        // 64 x 68

    const int tid = threadIdx.x;
    const int tx  = tid & 15;
    const int ty  = tid >> 4;
    const int q0  = blockIdx.x << 6;
    const int h   = blockIdx.y;
    const int b   = blockIdx.z;
    const int hk  = h >> 2;             // rep = HQ/HKV = 4

    const float* Qp = Qg + ((size_t)(b * HQ_ + h) * T_ + q0) * DH_;
    const float* Kp = Kg + ((size_t)(b * HKV_ + hk) * T_) * DH_;
    const float* Vp = Vg + ((size_t)(b * HKV_ + hk) * T_) * DH_;

    const float qsc = 0.08838834764831845f;  // 1/sqrt(128)
    for (int li = tid; li < 64 * 32; li += 256) {
        const int r  = li >> 5;
        const int c4 = (li & 31) << 2;
        float4 v = *(const float4*)(Qp + (size_t)r * DH_ + c4);
        float* d = Qs + r * QS_ + c4;
        d[0] = v.x * qsc; d[1] = v.y * qsc; d[2] = v.z * qsc; d[3] = v.w * qsc;
    }

    float m_i[4], l_i[4], acc[4][8];
#pragma unroll
    for (int i = 0; i < 4; i++) {
        m_i[i] = -1e30f; l_i[i] = 0.f;
#pragma unroll
        for (int j = 0; j < 8; j++) acc[i][j] = 0.f;
    }

    int lo = q0 - (WIN_ - 1); if (lo < 0) lo = 0;
    const int kt0 = lo >> 6;
    const int kt1 = q0 >> 6;

    const float* qrow0 = Qs + (ty * 4 + 0) * QS_;
    const float* qrow1 = Qs + (ty * 4 + 1) * QS_;
    const float* qrow2 = Qs + (ty * 4 + 2) * QS_;
    const float* qrow3 = Qs + (ty * 4 + 3) * QS_;
    const float* krow0 = Ks + (tx * 4 + 0) * QS_;
    const float* krow1 = Ks + (tx * 4 + 1) * QS_;
    const float* krow2 = Ks + (tx * 4 + 2) * QS_;
    const float* krow3 = Ks + (tx * 4 + 3) * QS_;

    for (int kt = kt0; kt <= kt1; ++kt) {
        const int k0 = kt << 6;

        // load K (transpose-padded) and V tiles
        for (int li = tid; li < 64 * 32; li += 256) {
            const int r  = li >> 5;
            const int c4 = (li & 31) << 2;
            float4 kv = *(const float4*)(Kp + (size_t)(k0 + r) * DH_ + c4);
            float* kd = Ks + r * QS_ + c4;
            kd[0] = kv.x; kd[1] = kv.y; kd[2] = kv.z; kd[3] = kv.w;
            *(float4*)(Vsm + r * VS_ + c4) =
                *(const float4*)(Vp + (size_t)(k0 + r) * DH_ + c4);
        }
        __syncthreads();

        // S = (Q/sqrt(d)) K^T
        float s[4][4];
#pragma unroll
        for (int i = 0; i < 4; i++)
#pragma unroll
            for (int j = 0; j < 4; j++) s[i][j] = 0.f;

#pragma unroll 8
        for (int d = 0; d < DH_; ++d) {
            float qa[4], kb[4];
            qa[0] = qrow0[d]; qa[1] = qrow1[d]; qa[2] = qrow2[d]; qa[3] = qrow3[d];
            kb[0] = krow0[d]; kb[1] = krow1[d]; kb[2] = krow2[d]; kb[3] = krow3[d];
#pragma unroll
            for (int i = 0; i < 4; i++)
#pragma unroll
                for (int j = 0; j < 4; j++)
                    s[i][j] += qa[i] * kb[j];
        }

        // mask + online softmax update, write P tile
#pragma unroll
        for (int i = 0; i < 4; i++) {
            const int qi = q0 + ty * 4 + i;
            float rmax = -1e30f;
#pragma unroll
            for (int j = 0; j < 4; j++) {
                const int kj = k0 + tx * 4 + j;
                const float sv = (qi >= kj && (qi - kj) < WIN_) ? s[i][j] : -1e30f;
                s[i][j] = sv;
                rmax = fmaxf(rmax, sv);
            }
#pragma unroll
            for (int off = 8; off; off >>= 1)
                rmax = fmaxf(rmax, __shfl_xor_sync(0xffffffffu, rmax, off));
            const float mn = fmaxf(m_i[i], rmax);

            float4 pv;
            pv.x = __expf(s[i][0] - mn);
            pv.y = __expf(s[i][1] - mn);
            pv.z = __expf(s[i][2] - mn);
            pv.w = __expf(s[i][3] - mn);
            float rs = pv.x + pv.y + pv.z + pv.w;
#pragma unroll
            for (int off = 8; off; off >>= 1)
                rs += __shfl_xor_sync(0xffffffffu, rs, off);

            const float sc = __expf(m_i[i] - mn);
            l_i[i] = l_i[i] * sc + rs;
            m_i[i] = mn;
#pragma unroll
            for (int j = 0; j < 8; j++) acc[i][j] *= sc;

            *(float4*)(Psm + (ty * 4 + i) * PS_ + (tx << 2)) = pv;
        }
        __syncthreads();

        // acc += P @ V
        const float* pr0 = Psm + (ty * 4 + 0) * PS_;
        const float* pr1 = Psm + (ty * 4 + 1) * PS_;
        const float* pr2 = Psm + (ty * 4 + 2) * PS_;
        const float* pr3 = Psm + (ty * 4 + 3) * PS_;
#pragma unroll 4
        for (int k = 0; k < 64; ++k) {
            float p[4];
            p[0] = pr0[k]; p[1] = pr1[k]; p[2] = pr2[k]; p[3] = pr3[k];
            float4 v0 = *(const float4*)(Vsm + k * VS_ + (tx << 3));
            float4 v1 = *(const float4*)(Vsm + k * VS_ + (tx << 3) + 4);
            float vv[8] = {v0.x, v0.y, v0.z, v0.w, v1.x, v1.y, v1.z, v1.w};
#pragma unroll
            for (int i = 0; i < 4; i++)
#pragma unroll
                for (int j = 0; j < 8; j++)
                    acc[i][j] += p[i] * vv[j];
        }
        __syncthreads();
    }

    // epilogue: y[b][t][h*128 + c] = acc / l
#pragma unroll
    for (int i = 0; i < 4; i++) {
        const float inv = 1.0f / l_i[i];
        const int t = q0 + ty * 4 + i;
        float* yp = Yg + ((size_t)(b * T_ + t)) * C_ + h * DH_ + (tx << 3);
        *(float4*)yp       = make_float4(acc[i][0] * inv, acc[i][1] * inv,
                                         acc[i][2] * inv, acc[i][3] * inv);
        *(float4*)(yp + 4) = make_float4(acc[i][4] * inv, acc[i][5] * inv,
                                         acc[i][6] * inv, acc[i][7] * inv);
    }
}

// ============================================================================
// launch
// ============================================================================
extern "C" void kernel_launch(void* const* d_in, const int* in_sizes, int n_in,
                              void* d_out, int out_size)
{
    const float* x      = (const float*)d_in[0];
    const float* w_qkv  = (const float*)d_in[1];
    const float* w_proj = (const float*)d_in[2];
    float* out = (float*)d_out;

    float *p_qkv, *p_Q, *p_K, *p_V, *p_y;
    cudaGetSymbolAddress((void**)&p_qkv, g_qkv);
    cudaGetSymbolAddress((void**)&p_Q,   g_Q);
    cudaGetSymbolAddress((void**)&p_K,   g_K);
    cudaGetSymbolAddress((void**)&p_V,   g_V);
    cudaGetSymbolAddress((void**)&p_y,   g_y);

    // 1) qkv = x @ w_qkv^T   (TF32 tensor cores)
    gemm_tf32<<<dim3(NQKV_ / BN_, MTOK_ / BM_), 256>>>(x, w_qkv, p_qkv, MTOK_, NQKV_, C_);

    // 2) RoPE + RMSNorm + split into Q/K/V head-major layouts
    rope_rms<<<dim3(HQ_ + 2 * HKV_, T_, B_), 64>>>(p_qkv, p_Q, p_K, p_V);

    // 3) sliding-window attention -> y in (B, T, C) layout
    cudaFuncSetAttribute(attn_kernel, cudaFuncAttributeMaxDynamicSharedMemorySize, ATTN_SMEM);
    attn_kernel<<<dim3(T_ / 64, HQ_, B_), 256, ATTN_SMEM>>>(p_Q, p_K, p_V, p_y);

    // 4) out = y @ w_proj^T  (TF32 tensor cores)
    gemm_tf32<<<dim3(C_ / BN_, MTOK_ / BM_), 256>>>(p_y, w_proj, out, MTOK_, C_, C_);
}

// round 4
// speedup vs baseline: 1.3089x; 1.1603x over previous
#include <cuda_runtime.h>
#include <cstdint>
#include <math.h>
#include <mma.h>

using namespace nvcuda;

#define B_    2
#define T_    2048
#define C_    2048
#define HQ_   16
#define HKV_  4
#define DH_   128
#define WIN_  512
#define NQKV_ 3072          // (HQ + 2*HKV) * DH
#define MTOK_ 4096          // B * T

// ---------------- scratch (static __device__, no allocations) ----------------
__device__ float g_qkv[MTOK_ * NQKV_];          // 50.3 MB
__device__ float g_Q[B_ * HQ_ * T_ * DH_];      // 33.5 MB
__device__ float g_K[B_ * HKV_ * T_ * DH_];     //  8.4 MB
__device__ float g_V[B_ * HKV_ * T_ * DH_];     //  8.4 MB
__device__ float g_y[MTOK_ * C_];               // 33.5 MB
__device__ float g_xr[MTOK_ * C_];              // 33.5 MB  x rounded to tf32
__device__ float g_wq[NQKV_ * C_];              // 25.2 MB  w_qkv rounded
__device__ float g_wp[C_ * C_];                 // 16.8 MB  w_proj rounded

// ============================================================================
// elementwise round-to-nearest tf32 (RNE) — makes GEMM inputs exactly
// tf32-representable so the cp.async GEMM path adds no extra error.
// ============================================================================
__global__ __launch_bounds__(256) void round_tf32(
    const float* __restrict__ in, float* __restrict__ out, int n4)
{
    const int i = blockIdx.x * blockDim.x + threadIdx.x;
    if (i >= n4) return;
    float4 v = ((const float4*)in)[i];
    v.x = wmma::__float_to_tf32(v.x);
    v.y = wmma::__float_to_tf32(v.y);
    v.z = wmma::__float_to_tf32(v.z);
    v.w = wmma::__float_to_tf32(v.w);
    ((float4*)out)[i] = v;
}

// ============================================================================
// TF32 tensor-core GEMM:  C[M,N] = A[M,K] @ B[N,K]^T  (row-major, K contig)
// 128x128 block tile, BK=16, 4-stage cp.async pipeline, 256 threads = 8 warps
// (2m x 4n), warp tile 64x32 = 4x2 wmma 16x16x8 fragments.
// Inputs must already be tf32-rounded.
// ============================================================================
#define BM_   128
#define BN_   128
#define GBK_  16
#define GPAD_ 20
#define GS_   4
#define GEMM_SMEM (GS_ * 128 * GPAD_ * 2 * (int)sizeof(float))

__device__ __forceinline__ void cp_async16(void* smem_dst, const void* gsrc) {
    unsigned int d = (unsigned int)__cvta_generic_to_shared(smem_dst);
    asm volatile("cp.async.cg.shared.global [%0], [%1], 16;\n" :: "r"(d), "l"(gsrc));
}

__global__ __launch_bounds__(256) void gemm_tf32(
    const float* __restrict__ A, const float* __restrict__ Bm,
    float* __restrict__ Cm, int M, int N, int K)
{
    extern __shared__ __align__(16) float gsm[];
    float (*As)[128][GPAD_] = (float (*)[128][GPAD_])gsm;
    float (*Bs)[128][GPAD_] = (float (*)[128][GPAD_])(gsm + GS_ * 128 * GPAD_);

    const int tid = threadIdx.x;
    const int wid = tid >> 5;
    const int m0  = blockIdx.y * BM_;
    const int n0  = blockIdx.x * BN_;
    const int wm  = (wid & 1) * 64;
    const int wn  = (wid >> 1) * 32;

    // load mapping: 16 floats/row = 4 float4; 256 thr cover 64 rows/pass
    const int lr = tid >> 2;            // 0..63
    const int lc = (tid & 3) << 2;      // 0,4,8,12

    const float* Abase = A  + (size_t)(m0 + lr) * K + lc;
    const float* Bbase = Bm + (size_t)(n0 + lr) * K + lc;
    const size_t rowK64 = (size_t)64 * K;

    wmma::fragment<wmma::accumulator, 16, 16, 8, float> acc[4][2];
#pragma unroll
    for (int i = 0; i < 4; i++)
#pragma unroll
        for (int j = 0; j < 2; j++)
            wmma::fill_fragment(acc[i][j], 0.0f);

    const int KT = K / GBK_;

    // ---- prologue: stages 0..GS_-2 ----
#pragma unroll
    for (int s = 0; s < GS_ - 1; ++s) {
        const size_t ko = (size_t)s * GBK_;
        cp_async16(&As[s][lr][lc],      Abase + ko);
        cp_async16(&As[s][lr + 64][lc], Abase + ko + rowK64);
        cp_async16(&Bs[s][lr][lc],      Bbase + ko);
        cp_async16(&Bs[s][lr + 64][lc], Bbase + ko + rowK64);
        asm volatile("cp.async.commit_group;\n" ::);
    }

    for (int kt = 0; kt < KT; ++kt) {
        asm volatile("cp.async.wait_group %0;\n" :: "n"(GS_ - 2));
        __syncthreads();

        // prefetch stage kt+GS_-1 into slot (kt+GS_-1)%GS_ (consumed GS_-1 iters ahead)
        if (kt + GS_ - 1 < KT) {
            const int ws = (kt + GS_ - 1) % GS_;
            const size_t ko = (size_t)(kt + GS_ - 1) * GBK_;
            cp_async16(&As[ws][lr][lc],      Abase + ko);
            cp_async16(&As[ws][lr + 64][lc], Abase + ko + rowK64);
            cp_async16(&Bs[ws][lr][lc],      Bbase + ko);
            cp_async16(&Bs[ws][lr + 64][lc], Bbase + ko + rowK64);
        }
        asm volatile("cp.async.commit_group;\n" ::);

        const int st = kt % GS_;
#pragma unroll
        for (int ks = 0; ks < 2; ++ks) {
            wmma::fragment<wmma::matrix_a, 16, 16, 8, wmma::precision::tf32, wmma::row_major> af[4];
            wmma::fragment<wmma::matrix_b, 16, 16, 8, wmma::precision::tf32, wmma::col_major> bf[2];
#pragma unroll
            for (int i = 0; i < 4; i++)
                wmma::load_matrix_sync(af[i], &As[st][wm + i * 16][ks * 8], GPAD_);
#pragma unroll
            for (int j = 0; j < 2; j++)
                wmma::load_matrix_sync(bf[j], &Bs[st][wn + j * 16][ks * 8], GPAD_);
#pragma unroll
            for (int i = 0; i < 4; i++)
#pragma unroll
                for (int j = 0; j < 2; j++)
                    wmma::mma_sync(acc[i][j], af[i], bf[j], acc[i][j]);
        }
    }

#pragma unroll
    for (int i = 0; i < 4; i++)
#pragma unroll
        for (int j = 0; j < 2; j++)
            wmma::store_matrix_sync(
                Cm + (size_t)(m0 + wm + i * 16) * N + (n0 + wn + j * 16),
                acc[i][j], N, wmma::mem_row_major);
}

// ============================================================================
// RoPE + RMSNorm + head split.  One block per (head, t, b), 64 threads.
// ============================================================================
__global__ __launch_bounds__(64) void rope_rms(
    const float* __restrict__ qkv,
    float* __restrict__ Qo, float* __restrict__ Ko, float* __restrict__ Vo)
{
    const int h = blockIdx.x;
    const int t = blockIdx.y;
    const int b = blockIdx.z;
    const int i = threadIdx.x;      // 0..63

    const float* src = qkv + ((size_t)(b * T_ + t)) * NQKV_ + h * DH_;
    float x0 = src[2 * i];
    float x1 = src[2 * i + 1];

    if (h >= HQ_ + HKV_) {          // V heads: plain copy/transpose
        float* dst = Vo + ((size_t)(b * HKV_ + (h - HQ_ - HKV_)) * T_ + t) * DH_;
        dst[2 * i]     = x0;
        dst[2 * i + 1] = x1;
        return;
    }

    const float inv_freq = powf(10000.0f, -(float)i * (1.0f / 64.0f));
    const float ang = (float)t * inv_freq;
    float sn, cs;
    sincosf(ang, &sn, &cs);
    const float y0 = x0 * cs - x1 * sn;
    const float y1 = x1 * cs + x0 * sn;

    float ss = y0 * y0 + y1 * y1;
#pragma unroll
    for (int off = 16; off; off >>= 1)
        ss += __shfl_xor_sync(0xffffffffu, ss, off);
    __shared__ float sh[2];
    if ((i & 31) == 0) sh[i >> 5] = ss;
    __syncthreads();
    const float rn = rsqrtf((sh[0] + sh[1]) * (1.0f / 128.0f) + 1.1920929e-07f);

    float* dst = (h < HQ_)
        ? Qo + ((size_t)(b * HQ_ + h) * T_ + t) * DH_
        : Ko + ((size_t)(b * HKV_ + (h - HQ_)) * T_ + t) * DH_;
    dst[2 * i]     = y0 * rn;
    dst[2 * i + 1] = y1 * rn;
}

// ============================================================================
// Sliding-window flash attention (unchanged from R1).
// ============================================================================
#define QS_ 129
#define VS_ 128
#define PS_ 68
#define ATTN_SMEM ((64 * QS_ * 2 + 64 * VS_ + 64 * PS_) * (int)sizeof(float))

__global__ __launch_bounds__(256) void attn_kernel(
    const float* __restrict__ Qg, const float* __restrict__ Kg,
    const float* __restrict__ Vg, float* __restrict__ Yg)
{
    extern __shared__ __align__(16) float sm[];
    float* Qs  = sm;                    // 64 x 129
    float* Ks  = Qs  + 64 * QS_;        // 64 x 129
    float* Vsm = Ks  + 64 * QS_;        // 64 x 128
    float* Psm = Vsm + 64 * VS_;        // 64 x 68

    const int tid = threadIdx.x;
    const int tx  = tid & 15;
    const int ty  = tid >> 4;
    const int q0  = blockIdx.x << 6;
    const int h   = blockIdx.y;
    const int b   = blockIdx.z;
    const int hk  = h >> 2;

    const float* Qp = Qg + ((size_t)(b * HQ_ + h) * T_ + q0) * DH_;
    const float* Kp = Kg + ((size_t)(b * HKV_ + hk) * T_) * DH_;
    const float* Vp = Vg + ((size_t)(b * HKV_ + hk) * T_) * DH_;

    const float qsc = 0.08838834764831845f;  // 1/sqrt(128)
    for (int li = tid; li < 64 * 32; li += 256) {
        const int r  = li >> 5;
        const int c4 = (li & 31) << 2;
        float4 v = *(const float4*)(Qp + (size_t)r * DH_ + c4);
        float* d = Qs + r * QS_ + c4;
        d[0] = v.x * qsc; d[1] = v.y * qsc; d[2] = v.z * qsc; d[3] = v.w * qsc;
    }

    float m_i[4], l_i[4], acc[4][8];
#pragma unroll
    for (int i = 0; i < 4; i++) {
        m_i[i] = -1e30f; l_i[i] = 0.f;
#pragma unroll
        for (int j = 0; j < 8; j++) acc[i][j] = 0.f;
    }

    int lo = q0 - (WIN_ - 1); if (lo < 0) lo = 0;
    const int kt0 = lo >> 6;
    const int kt1 = q0 >> 6;

    const float* qrow0 = Qs + (ty * 4 + 0) * QS_;
    const float* qrow1 = Qs + (ty * 4 + 1) * QS_;
    const float* qrow2 = Qs + (ty * 4 + 2) * QS_;
    const float* qrow3 = Qs + (ty * 4 + 3) * QS_;
    const float* krow0 = Ks + (tx * 4 + 0) * QS_;
    const float* krow1 = Ks + (tx * 4 + 1) * QS_;
    const float* krow2 = Ks + (tx * 4 + 2) * QS_;
    const float* krow3 = Ks + (tx * 4 + 3) * QS_;

    for (int kt = kt0; kt <= kt1; ++kt) {
        const int k0 = kt << 6;

        for (int li = tid; li < 64 * 32; li += 256) {
            const int r  = li >> 5;
            const int c4 = (li & 31) << 2;
            float4 kv = *(const float4*)(Kp + (size_t)(k0 + r) * DH_ + c4);
            float* kd = Ks + r * QS_ + c4;
            kd[0] = kv.x; kd[1] = kv.y; kd[2] = kv.z; kd[3] = kv.w;
            *(float4*)(Vsm + r * VS_ + c4) =
                *(const float4*)(Vp + (size_t)(k0 + r) * DH_ + c4);
        }
        __syncthreads();

        float s[4][4];
#pragma unroll
        for (int i = 0; i < 4; i++)
#pragma unroll
            for (int j = 0; j < 4; j++) s[i][j] = 0.f;

#pragma unroll 8
        for (int d = 0; d < DH_; ++d) {
            float qa[4], kb[4];
            qa[0] = qrow0[d]; qa[1] = qrow1[d]; qa[2] = qrow2[d]; qa[3] = qrow3[d];
            kb[0] = krow0[d]; kb[1] = krow1[d]; kb[2] = krow2[d]; kb[3] = krow3[d];
#pragma unroll
            for (int i = 0; i < 4; i++)
#pragma unroll
                for (int j = 0; j < 4; j++)
                    s[i][j] += qa[i] * kb[j];
        }

#pragma unroll
        for (int i = 0; i < 4; i++) {
            const int qi = q0 + ty * 4 + i;
            float rmax = -1e30f;
#pragma unroll
            for (int j = 0; j < 4; j++) {
                const int kj = k0 + tx * 4 + j;
                const float sv = (qi >= kj && (qi - kj) < WIN_) ? s[i][j] : -1e30f;
                s[i][j] = sv;
                rmax = fmaxf(rmax, sv);
            }
#pragma unroll
            for (int off = 8; off; off >>= 1)
                rmax = fmaxf(rmax, __shfl_xor_sync(0xffffffffu, rmax, off));
            const float mn = fmaxf(m_i[i], rmax);

            float4 pv;
            pv.x = __expf(s[i][0] - mn);
            pv.y = __expf(s[i][1] - mn);
            pv.z = __expf(s[i][2] - mn);
            pv.w = __expf(s[i][3] - mn);
            float rs = pv.x + pv.y + pv.z + pv.w;
#pragma unroll
            for (int off = 8; off; off >>= 1)
                rs += __shfl_xor_sync(0xffffffffu, rs, off);

            const float sc = __expf(m_i[i] - mn);
            l_i[i] = l_i[i] * sc + rs;
            m_i[i] = mn;
#pragma unroll
            for (int j = 0; j < 8; j++) acc[i][j] *= sc;

            *(float4*)(Psm + (ty * 4 + i) * PS_ + (tx << 2)) = pv;
        }
        __syncthreads();

        const float* pr0 = Psm + (ty * 4 + 0) * PS_;
        const float* pr1 = Psm + (ty * 4 + 1) * PS_;
        const float* pr2 = Psm + (ty * 4 + 2) * PS_;
        const float* pr3 = Psm + (ty * 4 + 3) * PS_;
#pragma unroll 4
        for (int k = 0; k < 64; ++k) {
            float p[4];
            p[0] = pr0[k]; p[1] = pr1[k]; p[2] = pr2[k]; p[3] = pr3[k];
            float4 v0 = *(const float4*)(Vsm + k * VS_ + (tx << 3));
            float4 v1 = *(const float4*)(Vsm + k * VS_ + (tx << 3) + 4);
            float vv[8] = {v0.x, v0.y, v0.z, v0.w, v1.x, v1.y, v1.z, v1.w};
#pragma unroll
            for (int i = 0; i < 4; i++)
#pragma unroll
                for (int j = 0; j < 8; j++)
                    acc[i][j] += p[i] * vv[j];
        }
        __syncthreads();
    }

#pragma unroll
    for (int i = 0; i < 4; i++) {
        const float inv = 1.0f / l_i[i];
        const int t = q0 + ty * 4 + i;
        float* yp = Yg + ((size_t)(b * T_ + t)) * C_ + h * DH_ + (tx << 3);
        *(float4*)yp       = make_float4(acc[i][0] * inv, acc[i][1] * inv,
                                         acc[i][2] * inv, acc[i][3] * inv);
        *(float4*)(yp + 4) = make_float4(acc[i][4] * inv, acc[i][5] * inv,
                                         acc[i][6] * inv, acc[i][7] * inv);
    }
}

// ============================================================================
// launch
// ============================================================================
extern "C" void kernel_launch(void* const* d_in, const int* in_sizes, int n_in,
                              void* d_out, int out_size)
{
    const float* x      = (const float*)d_in[0];
    const float* w_qkv  = (const float*)d_in[1];
    const float* w_proj = (const float*)d_in[2];
    float* out = (float*)d_out;

    float *p_qkv, *p_Q, *p_K, *p_V, *p_y, *p_xr, *p_wq, *p_wp;
    cudaGetSymbolAddress((void**)&p_qkv, g_qkv);
    cudaGetSymbolAddress((void**)&p_Q,   g_Q);
    cudaGetSymbolAddress((void**)&p_K,   g_K);
    cudaGetSymbolAddress((void**)&p_V,   g_V);
    cudaGetSymbolAddress((void**)&p_y,   g_y);
    cudaGetSymbolAddress((void**)&p_xr,  g_xr);
    cudaGetSymbolAddress((void**)&p_wq,  g_wq);
    cudaGetSymbolAddress((void**)&p_wp,  g_wp);

    cudaFuncSetAttribute(gemm_tf32, cudaFuncAttributeMaxDynamicSharedMemorySize, GEMM_SMEM);
    cudaFuncSetAttribute(attn_kernel, cudaFuncAttributeMaxDynamicSharedMemorySize, ATTN_SMEM);

    // 0) round GEMM inputs to tf32 (RNE)
    round_tf32<<<(MTOK_ * C_ / 4 + 255) / 256, 256>>>(x, p_xr, MTOK_ * C_ / 4);
    round_tf32<<<(NQKV_ * C_ / 4 + 255) / 256, 256>>>(w_qkv, p_wq, NQKV_ * C_ / 4);
    round_tf32<<<(C_ * C_ / 4 + 255) / 256, 256>>>(w_proj, p_wp, C_ * C_ / 4);

    // 1) qkv = x @ w_qkv^T   (TF32 tensor cores, cp.async pipeline)
    gemm_tf32<<<dim3(NQKV_ / BN_, MTOK_ / BM_), 256, GEMM_SMEM>>>(
        p_xr, p_wq, p_qkv, MTOK_, NQKV_, C_);

    // 2) RoPE + RMSNorm + split into Q/K/V head-major layouts
    rope_rms<<<dim3(HQ_ + 2 * HKV_, T_, B_), 64>>>(p_qkv, p_Q, p_K, p_V);

    // 3) sliding-window attention -> y in (B, T, C) layout
    attn_kernel<<<dim3(T_ / 64, HQ_, B_), 256, ATTN_SMEM>>>(p_Q, p_K, p_V, p_y);

    // 4) round y, then out = y @ w_proj^T
    round_tf32<<<(MTOK_ * C_ / 4 + 255) / 256, 256>>>(p_y, p_y, MTOK_ * C_ / 4);
    gemm_tf32<<<dim3(C_ / BN_, MTOK_ / BM_), 256, GEMM_SMEM>>>(
        p_y, p_wp, out, MTOK_, C_, C_);
}

// round 6
// speedup vs baseline: 1.4549x; 1.1115x over previous
#include <cuda_runtime.h>
#include <cstdint>
#include <math.h>
#include <mma.h>

using namespace nvcuda;

#define B_    2
#define T_    2048
#define C_    2048
#define HQ_   16
#define HKV_  4
#define DH_   128
#define WIN_  512
#define NQKV_ 3072          // (HQ + 2*HKV) * DH
#define MTOK_ 4096          // B * T

// ---------------- scratch (static __device__, no allocations) ----------------
__device__ float g_qkv[MTOK_ * NQKV_];
__device__ float g_Q[B_ * HQ_ * T_ * DH_];
__device__ float g_K[B_ * HKV_ * T_ * DH_];
__device__ float g_V[B_ * HKV_ * T_ * DH_];
__device__ float g_y[MTOK_ * C_];
__device__ float g_xr[MTOK_ * C_];
__device__ float g_wq[NQKV_ * C_];
__device__ float g_wp[C_ * C_];

// ============================================================================
// elementwise round-to-nearest tf32 (RNE)
// ============================================================================
__global__ __launch_bounds__(256) void round_tf32(
    const float* __restrict__ in, float* __restrict__ out, int n4)
{
    const int i = blockIdx.x * blockDim.x + threadIdx.x;
    if (i >= n4) return;
    float4 v = ((const float4*)in)[i];
    v.x = wmma::__float_to_tf32(v.x);
    v.y = wmma::__float_to_tf32(v.y);
    v.z = wmma::__float_to_tf32(v.z);
    v.w = wmma::__float_to_tf32(v.w);
    ((float4*)out)[i] = v;
}

// ============================================================================
// TF32 tensor-core GEMM (R4 config, unchanged):  C = A @ B^T, 128x128 tile,
// BK=16, 4-stage cp.async pipeline, 8 warps, warp tile 64x32.
// ============================================================================
#define BM_   128
#define BN_   128
#define GBK_  16
#define GPAD_ 20
#define GS_   4
#define GEMM_SMEM (GS_ * 128 * GPAD_ * 2 * (int)sizeof(float))

__device__ __forceinline__ void cp_async16(void* smem_dst, const void* gsrc) {
    unsigned int d = (unsigned int)__cvta_generic_to_shared(smem_dst);
    asm volatile("cp.async.cg.shared.global [%0], [%1], 16;\n" :: "r"(d), "l"(gsrc));
}

__global__ __launch_bounds__(256) void gemm_tf32(
    const float* __restrict__ A, const float* __restrict__ Bm,
    float* __restrict__ Cm, int M, int N, int K)
{
    extern __shared__ __align__(16) float gsm[];
    float (*As)[128][GPAD_] = (float (*)[128][GPAD_])gsm;
    float (*Bs)[128][GPAD_] = (float (*)[128][GPAD_])(gsm + GS_ * 128 * GPAD_);

    const int tid = threadIdx.x;
    const int wid = tid >> 5;
    const int m0  = blockIdx.y * BM_;
    const int n0  = blockIdx.x * BN_;
    const int wm  = (wid & 1) * 64;
    const int wn  = (wid >> 1) * 32;

    const int lr = tid >> 2;
    const int lc = (tid & 3) << 2;

    const float* Abase = A  + (size_t)(m0 + lr) * K + lc;
    const float* Bbase = Bm + (size_t)(n0 + lr) * K + lc;
    const size_t rowK64 = (size_t)64 * K;

    wmma::fragment<wmma::accumulator, 16, 16, 8, float> acc[4][2];
#pragma unroll
    for (int i = 0; i < 4; i++)
#pragma unroll
        for (int j = 0; j < 2; j++)
            wmma::fill_fragment(acc[i][j], 0.0f);

    const int KT = K / GBK_;

#pragma unroll
    for (int s = 0; s < GS_ - 1; ++s) {
        const size_t ko = (size_t)s * GBK_;
        cp_async16(&As[s][lr][lc],      Abase + ko);
        cp_async16(&As[s][lr + 64][lc], Abase + ko + rowK64);
        cp_async16(&Bs[s][lr][lc],      Bbase + ko);
        cp_async16(&Bs[s][lr + 64][lc], Bbase + ko + rowK64);
        asm volatile("cp.async.commit_group;\n" ::);
    }

    for (int kt = 0; kt < KT; ++kt) {
        asm volatile("cp.async.wait_group %0;\n" :: "n"(GS_ - 2));
        __syncthreads();

        if (kt + GS_ - 1 < KT) {
            const int ws = (kt + GS_ - 1) % GS_;
            const size_t ko = (size_t)(kt + GS_ - 1) * GBK_;
            cp_async16(&As[ws][lr][lc],      Abase + ko);
            cp_async16(&As[ws][lr + 64][lc], Abase + ko + rowK64);
            cp_async16(&Bs[ws][lr][lc],      Bbase + ko);
            cp_async16(&Bs[ws][lr + 64][lc], Bbase + ko + rowK64);
        }
        asm volatile("cp.async.commit_group;\n" ::);

        const int st = kt % GS_;
#pragma unroll
        for (int ks = 0; ks < 2; ++ks) {
            wmma::fragment<wmma::matrix_a, 16, 16, 8, wmma::precision::tf32, wmma::row_major> af[4];
            wmma::fragment<wmma::matrix_b, 16, 16, 8, wmma::precision::tf32, wmma::col_major> bf[2];
#pragma unroll
            for (int i = 0; i < 4; i++)
                wmma::load_matrix_sync(af[i], &As[st][wm + i * 16][ks * 8], GPAD_);
#pragma unroll
            for (int j = 0; j < 2; j++)
                wmma::load_matrix_sync(bf[j], &Bs[st][wn + j * 16][ks * 8], GPAD_);
#pragma unroll
            for (int i = 0; i < 4; i++)
#pragma unroll
                for (int j = 0; j < 2; j++)
                    wmma::mma_sync(acc[i][j], af[i], bf[j], acc[i][j]);
        }
    }

#pragma unroll
    for (int i = 0; i < 4; i++)
#pragma unroll
        for (int j = 0; j < 2; j++)
            wmma::store_matrix_sync(
                Cm + (size_t)(m0 + wm + i * 16) * N + (n0 + wn + j * 16),
                acc[i][j], N, wmma::mem_row_major);
}

// ============================================================================
// RoPE + RMSNorm + head split (unchanged).
// ============================================================================
__global__ __launch_bounds__(64) void rope_rms(
    const float* __restrict__ qkv,
    float* __restrict__ Qo, float* __restrict__ Ko, float* __restrict__ Vo)
{
    const int h = blockIdx.x;
    const int t = blockIdx.y;
    const int b = blockIdx.z;
    const int i = threadIdx.x;

    const float* src = qkv + ((size_t)(b * T_ + t)) * NQKV_ + h * DH_;
    float x0 = src[2 * i];
    float x1 = src[2 * i + 1];

    if (h >= HQ_ + HKV_) {
        float* dst = Vo + ((size_t)(b * HKV_ + (h - HQ_ - HKV_)) * T_ + t) * DH_;
        dst[2 * i]     = x0;
        dst[2 * i + 1] = x1;
        return;
    }

    const float inv_freq = powf(10000.0f, -(float)i * (1.0f / 64.0f));
    const float ang = (float)t * inv_freq;
    float sn, cs;
    sincosf(ang, &sn, &cs);
    const float y0 = x0 * cs - x1 * sn;
    const float y1 = x1 * cs + x0 * sn;

    float ss = y0 * y0 + y1 * y1;
#pragma unroll
    for (int off = 16; off; off >>= 1)
        ss += __shfl_xor_sync(0xffffffffu, ss, off);
    __shared__ float sh[2];
    if ((i & 31) == 0) sh[i >> 5] = ss;
    __syncthreads();
    const float rn = rsqrtf((sh[0] + sh[1]) * (1.0f / 128.0f) + 1.1920929e-07f);

    float* dst = (h < HQ_)
        ? Qo + ((size_t)(b * HQ_ + h) * T_ + t) * DH_
        : Ko + ((size_t)(b * HKV_ + (h - HQ_)) * T_ + t) * DH_;
    dst[2 * i]     = y0 * rn;
    dst[2 * i + 1] = y1 * rn;
}

// ============================================================================
// Sliding-window flash attention, S and PV on wmma TF32 tensor cores.
// Tile 64q x 64k, DH=128.  256 threads = 8 warps.
//   S:  warps 2(m) x 4(n), warp tile 32q x 16k, K-loop over DH.
//   softmax: SIMT on the S smem tile (16x16 threads, 4 rows x 4 cols each).
//   PV: warps 2(m) x 4(n), warp tile 32q x 32d, staged to smem (reuses K buf),
//       merged into SIMT per-row accumulators with online-softmax rescale.
// ============================================================================
#define AQL_ 132            // Q/K/V ld (pad 128+4)
#define APL_ 72             // S/P ld (pad 64+8)
#define ATTN_SMEM ((3 * 64 * AQL_ + 64 * APL_) * (int)sizeof(float))

__global__ __launch_bounds__(256) void attn_tc(
    const float* __restrict__ Qg, const float* __restrict__ Kg,
    const float* __restrict__ Vg, float* __restrict__ Yg)
{
    extern __shared__ __align__(16) float sm[];
    float* Qs = sm;                    // 64 x 132
    float* Ks = Qs + 64 * AQL_;        // 64 x 132 (reused as O staging)
    float* Vs = Ks + 64 * AQL_;        // 64 x 132
    float* Ps = Vs + 64 * AQL_;        // 64 x 72

    const int tid = threadIdx.x;
    const int tx  = tid & 15;
    const int ty  = tid >> 4;
    const int wid = tid >> 5;
    const int q0  = blockIdx.x << 6;
    const int h   = blockIdx.y;
    const int b   = blockIdx.z;
    const int hk  = h >> 2;

    const float* Qp = Qg + ((size_t)(b * HQ_ + h) * T_ + q0) * DH_;
    const float* Kp = Kg + ((size_t)(b * HKV_ + hk) * T_) * DH_;
    const float* Vp = Vg + ((size_t)(b * HKV_ + hk) * T_) * DH_;

    const float qsc = 0.08838834764831845f;  // 1/sqrt(128)
    for (int li = tid; li < 64 * 32; li += 256) {
        const int r  = li >> 5;
        const int c4 = (li & 31) << 2;
        float4 v = *(const float4*)(Qp + (size_t)r * DH_ + c4);
        float* d = Qs + r * AQL_ + c4;
        d[0] = wmma::__float_to_tf32(v.x * qsc);
        d[1] = wmma::__float_to_tf32(v.y * qsc);
        d[2] = wmma::__float_to_tf32(v.z * qsc);
        d[3] = wmma::__float_to_tf32(v.w * qsc);
    }

    float m_i[4], l_i[4], acc[4][8];
#pragma unroll
    for (int i = 0; i < 4; i++) {
        m_i[i] = -1e30f; l_i[i] = 0.f;
#pragma unroll
        for (int j = 0; j < 8; j++) acc[i][j] = 0.f;
    }

    int lo = q0 - (WIN_ - 1); if (lo < 0) lo = 0;
    const int kt0 = lo >> 6;
    const int kt1 = q0 >> 6;

    for (int kt = kt0; kt <= kt1; ++kt) {
        const int k0 = kt << 6;

        // ---- load K, V tiles (tf32-rounded) ----
        for (int li = tid; li < 64 * 32; li += 256) {
            const int r  = li >> 5;
            const int c4 = (li & 31) << 2;
            float4 kv = *(const float4*)(Kp + (size_t)(k0 + r) * DH_ + c4);
            float4 vv = *(const float4*)(Vp + (size_t)(k0 + r) * DH_ + c4);
            float* kd = Ks + r * AQL_ + c4;
            float* vd = Vs + r * AQL_ + c4;
            kd[0] = wmma::__float_to_tf32(kv.x);
            kd[1] = wmma::__float_to_tf32(kv.y);
            kd[2] = wmma::__float_to_tf32(kv.z);
            kd[3] = wmma::__float_to_tf32(kv.w);
            vd[0] = wmma::__float_to_tf32(vv.x);
            vd[1] = wmma::__float_to_tf32(vv.y);
            vd[2] = wmma::__float_to_tf32(vv.z);
            vd[3] = wmma::__float_to_tf32(vv.w);
        }
        __syncthreads();

        // ---- S = Q K^T via wmma: warp (wy, wx) does 32q x 16k ----
        {
            const int wy = wid & 1;
            const int wx = wid >> 1;
            wmma::fragment<wmma::accumulator, 16, 16, 8, float> sacc[2];
            wmma::fill_fragment(sacc[0], 0.0f);
            wmma::fill_fragment(sacc[1], 0.0f);
#pragma unroll
            for (int d = 0; d < DH_; d += 8) {
                wmma::fragment<wmma::matrix_a, 16, 16, 8, wmma::precision::tf32, wmma::row_major> af[2];
                wmma::fragment<wmma::matrix_b, 16, 16, 8, wmma::precision::tf32, wmma::col_major> bf;
                wmma::load_matrix_sync(af[0], Qs + (wy * 32 + 0)  * AQL_ + d, AQL_);
                wmma::load_matrix_sync(af[1], Qs + (wy * 32 + 16) * AQL_ + d, AQL_);
                wmma::load_matrix_sync(bf,    Ks + (wx * 16) * AQL_ + d, AQL_);
                wmma::mma_sync(sacc[0], af[0], bf, sacc[0]);
                wmma::mma_sync(sacc[1], af[1], bf, sacc[1]);
            }
            wmma::store_matrix_sync(Ps + (wy * 32 + 0)  * APL_ + wx * 16, sacc[0], APL_, wmma::mem_row_major);
            wmma::store_matrix_sync(Ps + (wy * 32 + 16) * APL_ + wx * 16, sacc[1], APL_, wmma::mem_row_major);
        }
        __syncthreads();

        // ---- softmax (SIMT): mask, online m/l update, write tf32 P ----
#pragma unroll
        for (int i = 0; i < 4; i++) {
            const int qi = q0 + ty * 4 + i;
            float* srow = Ps + (ty * 4 + i) * APL_ + (tx << 2);
            float s0 = srow[0], s1 = srow[1], s2 = srow[2], s3 = srow[3];
            const int kj = k0 + (tx << 2);
            s0 = (qi >= kj + 0 && (qi - kj - 0) < WIN_) ? s0 : -1e30f;
            s1 = (qi >= kj + 1 && (qi - kj - 1) < WIN_) ? s1 : -1e30f;
            s2 = (qi >= kj + 2 && (qi - kj - 2) < WIN_) ? s2 : -1e30f;
            s3 = (qi >= kj + 3 && (qi - kj - 3) < WIN_) ? s3 : -1e30f;
            float rmax = fmaxf(fmaxf(s0, s1), fmaxf(s2, s3));
#pragma unroll
            for (int off = 8; off; off >>= 1)
                rmax = fmaxf(rmax, __shfl_xor_sync(0xffffffffu, rmax, off));
            const float mn = fmaxf(m_i[i], rmax);

            float p0 = __expf(s0 - mn), p1 = __expf(s1 - mn);
            float p2 = __expf(s2 - mn), p3 = __expf(s3 - mn);
            float rs = p0 + p1 + p2 + p3;
#pragma unroll
            for (int off = 8; off; off >>= 1)
                rs += __shfl_xor_sync(0xffffffffu, rs, off);

            const float sc = __expf(m_i[i] - mn);
            l_i[i] = l_i[i] * sc + rs;
            m_i[i] = mn;
#pragma unroll
            for (int j = 0; j < 8; j++) acc[i][j] *= sc;

            srow[0] = wmma::__float_to_tf32(p0);
            srow[1] = wmma::__float_to_tf32(p1);
            srow[2] = wmma::__float_to_tf32(p2);
            srow[3] = wmma::__float_to_tf32(p3);
        }
        __syncthreads();

        // ---- O_tile = P V via wmma: warp (wm, wn) does 32q x 32d -> Ks ----
        {
            const int wm = (wid & 1) * 32;
            const int wn = (wid >> 1) * 32;
            wmma::fragment<wmma::accumulator, 16, 16, 8, float> oacc[2][2];
#pragma unroll
            for (int i = 0; i < 2; i++)
#pragma unroll
                for (int j = 0; j < 2; j++)
                    wmma::fill_fragment(oacc[i][j], 0.0f);
#pragma unroll
            for (int k = 0; k < 64; k += 8) {
                wmma::fragment<wmma::matrix_a, 16, 16, 8, wmma::precision::tf32, wmma::row_major> af[2];
                wmma::fragment<wmma::matrix_b, 16, 16, 8, wmma::precision::tf32, wmma::row_major> bf[2];
                wmma::load_matrix_sync(af[0], Ps + (wm + 0)  * APL_ + k, APL_);
                wmma::load_matrix_sync(af[1], Ps + (wm + 16) * APL_ + k, APL_);
                wmma::load_matrix_sync(bf[0], Vs + k * AQL_ + wn + 0,  AQL_);
                wmma::load_matrix_sync(bf[1], Vs + k * AQL_ + wn + 16, AQL_);
#pragma unroll
                for (int i = 0; i < 2; i++)
#pragma unroll
                    for (int j = 0; j < 2; j++)
                        wmma::mma_sync(oacc[i][j], af[i], bf[j], oacc[i][j]);
            }
#pragma unroll
            for (int i = 0; i < 2; i++)
#pragma unroll
                for (int j = 0; j < 2; j++)
                    wmma::store_matrix_sync(
                        Ks + (wm + i * 16) * AQL_ + wn + j * 16,
                        oacc[i][j], AQL_, wmma::mem_row_major);
        }
        __syncthreads();

        // ---- merge staged O tile into SIMT accumulators ----
#pragma unroll
        for (int i = 0; i < 4; i++) {
            const float* orow = Ks + (ty * 4 + i) * AQL_ + (tx << 3);
#pragma unroll
            for (int j = 0; j < 8; j++) acc[i][j] += orow[j];
        }
        __syncthreads();   // Ks reloaded next iteration
    }

    // epilogue: y = acc / l, rounded to tf32 (feeds the proj GEMM directly)
#pragma unroll
    for (int i = 0; i < 4; i++) {
        const float inv = 1.0f / l_i[i];
        const int t = q0 + ty * 4 + i;
        float* yp = Yg + ((size_t)(b * T_ + t)) * C_ + h * DH_ + (tx << 3);
        *(float4*)yp = make_float4(
            wmma::__float_to_tf32(acc[i][0] * inv), wmma::__float_to_tf32(acc[i][1] * inv),
            wmma::__float_to_tf32(acc[i][2] * inv), wmma::__float_to_tf32(acc[i][3] * inv));
        *(float4*)(yp + 4) = make_float4(
            wmma::__float_to_tf32(acc[i][4] * inv), wmma::__float_to_tf32(acc[i][5] * inv),
            wmma::__float_to_tf32(acc[i][6] * inv), wmma::__float_to_tf32(acc[i][7] * inv));
    }
}

// ============================================================================
// launch
// ============================================================================
extern "C" void kernel_launch(void* const* d_in, const int* in_sizes, int n_in,
                              void* d_out, int out_size)
{
    const float* x      = (const float*)d_in[0];
    const float* w_qkv  = (const float*)d_in[1];
    const float* w_proj = (const float*)d_in[2];
    float* out = (float*)d_out;

    float *p_qkv, *p_Q, *p_K, *p_V, *p_y, *p_xr, *p_wq, *p_wp;
    cudaGetSymbolAddress((void**)&p_qkv, g_qkv);
    cudaGetSymbolAddress((void**)&p_Q,   g_Q);
    cudaGetSymbolAddress((void**)&p_K,   g_K);
    cudaGetSymbolAddress((void**)&p_V,   g_V);
    cudaGetSymbolAddress((void**)&p_y,   g_y);
    cudaGetSymbolAddress((void**)&p_xr,  g_xr);
    cudaGetSymbolAddress((void**)&p_wq,  g_wq);
    cudaGetSymbolAddress((void**)&p_wp,  g_wp);

    cudaFuncSetAttribute(gemm_tf32, cudaFuncAttributeMaxDynamicSharedMemorySize, GEMM_SMEM);
    cudaFuncSetAttribute(attn_tc, cudaFuncAttributeMaxDynamicSharedMemorySize, ATTN_SMEM);

    // 0) round GEMM inputs to tf32 (RNE)
    round_tf32<<<(MTOK_ * C_ / 4 + 255) / 256, 256>>>(x, p_xr, MTOK_ * C_ / 4);
    round_tf32<<<(NQKV_ * C_ / 4 + 255) / 256, 256>>>(w_qkv, p_wq, NQKV_ * C_ / 4);
    round_tf32<<<(C_ * C_ / 4 + 255) / 256, 256>>>(w_proj, p_wp, C_ * C_ / 4);

    // 1) qkv = x @ w_qkv^T
    gemm_tf32<<<dim3(NQKV_ / BN_, MTOK_ / BM_), 256, GEMM_SMEM>>>(
        p_xr, p_wq, p_qkv, MTOK_, NQKV_, C_);

    // 2) RoPE + RMSNorm + split
    rope_rms<<<dim3(HQ_ + 2 * HKV_, T_, B_), 64>>>(p_qkv, p_Q, p_K, p_V);

    // 3) attention (tensor-core S/PV); y written tf32-rounded
    attn_tc<<<dim3(T_ / 64, HQ_, B_), 256, ATTN_SMEM>>>(p_Q, p_K, p_V, p_y);

    // 4) out = y @ w_proj^T
    gemm_tf32<<<dim3(C_ / BN_, MTOK_ / BM_), 256, GEMM_SMEM>>>(
        p_y, p_wp, out, MTOK_, C_, C_);
}

// round 7
// speedup vs baseline: 1.5419x; 1.0598x over previous
#include <cuda_runtime.h>
#include <cstdint>
#include <math.h>
#include <mma.h>

using namespace nvcuda;

#define B_    2
#define T_    2048
#define C_    2048
#define HQ_   16
#define HKV_  4
#define DH_   128
#define WIN_  512
#define NQKV_ 3072          // (HQ + 2*HKV) * DH
#define MTOK_ 4096          // B * T

// ---------------- scratch (static __device__, no allocations) ----------------
__device__ float g_qkv[MTOK_ * NQKV_];
__device__ float g_Q[B_ * HQ_ * T_ * DH_];
__device__ float g_K[B_ * HKV_ * T_ * DH_];
__device__ float g_V[B_ * HKV_ * T_ * DH_];
__device__ float g_y[MTOK_ * C_];
__device__ float g_xr[MTOK_ * C_];
__device__ float g_wq[NQKV_ * C_];
__device__ float g_wp[C_ * C_];

// ============================================================================
// elementwise round-to-nearest tf32 (RNE)
// ============================================================================
__global__ __launch_bounds__(256) void round_tf32(
    const float* __restrict__ in, float* __restrict__ out, int n4)
{
    const int i = blockIdx.x * blockDim.x + threadIdx.x;
    if (i >= n4) return;
    float4 v = ((const float4*)in)[i];
    v.x = wmma::__float_to_tf32(v.x);
    v.y = wmma::__float_to_tf32(v.y);
    v.z = wmma::__float_to_tf32(v.z);
    v.w = wmma::__float_to_tf32(v.w);
    ((float4*)out)[i] = v;
}

// ============================================================================
// TF32 tensor-core GEMM:  C = A @ B^T.  CTA tile 128x256, BK=16, 3-stage
// cp.async pipeline, 8 warps in 2(m) x 4(n), warp tile 64x64 = 4x4 wmma
// fragments (2x the MMA work per fragment-load byte vs 64x32 -> smem-BW
// bound becomes compute bound).
// ============================================================================
#define BM_   128
#define BN_   256
#define GBK_  16
#define GPAD_ 20
#define GS_   3
#define GEMM_SMEM (GS_ * (BM_ + BN_) * GPAD_ * (int)sizeof(float))

__device__ __forceinline__ void cp_async16(void* smem_dst, const void* gsrc) {
    unsigned int d = (unsigned int)__cvta_generic_to_shared(smem_dst);
    asm volatile("cp.async.cg.shared.global [%0], [%1], 16;\n" :: "r"(d), "l"(gsrc));
}

__global__ __launch_bounds__(256, 1) void gemm_tf32(
    const float* __restrict__ A, const float* __restrict__ Bm,
    float* __restrict__ Cm, int M, int N, int K)
{
    extern __shared__ __align__(16) float gsm[];
    float (*As)[BM_][GPAD_] = (float (*)[BM_][GPAD_])gsm;
    float (*Bs)[BN_][GPAD_] = (float (*)[BN_][GPAD_])(gsm + GS_ * BM_ * GPAD_);

    const int tid = threadIdx.x;
    const int wid = tid >> 5;
    const int m0  = blockIdx.y * BM_;
    const int n0  = blockIdx.x * BN_;
    const int wm  = (wid & 1) * 64;     // 2 warps over 128 m
    const int wn  = (wid >> 1) * 64;    // 4 warps over 256 n

    // load mapping: 16 floats/row = 4 float4; 256 thr cover 64 rows/pass
    const int lr = tid >> 2;            // 0..63
    const int lc = (tid & 3) << 2;      // 0,4,8,12

    const float* Abase = A  + (size_t)(m0 + lr) * K + lc;
    const float* Bbase = Bm + (size_t)(n0 + lr) * K + lc;
    const size_t rowK64 = (size_t)64 * K;

    wmma::fragment<wmma::accumulator, 16, 16, 8, float> acc[4][4];
#pragma unroll
    for (int i = 0; i < 4; i++)
#pragma unroll
        for (int j = 0; j < 4; j++)
            wmma::fill_fragment(acc[i][j], 0.0f);

    const int KT = K / GBK_;

    // ---- prologue: stages 0..GS_-2 ----
#pragma unroll
    for (int s = 0; s < GS_ - 1; ++s) {
        const size_t ko = (size_t)s * GBK_;
        cp_async16(&As[s][lr][lc],       Abase + ko);
        cp_async16(&As[s][lr + 64][lc],  Abase + ko + rowK64);
        cp_async16(&Bs[s][lr][lc],       Bbase + ko);
        cp_async16(&Bs[s][lr + 64][lc],  Bbase + ko + rowK64);
        cp_async16(&Bs[s][lr + 128][lc], Bbase + ko + 2 * rowK64);
        cp_async16(&Bs[s][lr + 192][lc], Bbase + ko + 3 * rowK64);
        asm volatile("cp.async.commit_group;\n" ::);
    }

    for (int kt = 0; kt < KT; ++kt) {
        asm volatile("cp.async.wait_group %0;\n" :: "n"(GS_ - 2));
        __syncthreads();

        if (kt + GS_ - 1 < KT) {
            const int ws = (kt + GS_ - 1) % GS_;
            const size_t ko = (size_t)(kt + GS_ - 1) * GBK_;
            cp_async16(&As[ws][lr][lc],       Abase + ko);
            cp_async16(&As[ws][lr + 64][lc],  Abase + ko + rowK64);
            cp_async16(&Bs[ws][lr][lc],       Bbase + ko);
            cp_async16(&Bs[ws][lr + 64][lc],  Bbase + ko + rowK64);
            cp_async16(&Bs[ws][lr + 128][lc], Bbase + ko + 2 * rowK64);
            cp_async16(&Bs[ws][lr + 192][lc], Bbase + ko + 3 * rowK64);
        }
        asm volatile("cp.async.commit_group;\n" ::);

        const int st = kt % GS_;
#pragma unroll
        for (int ks = 0; ks < 2; ++ks) {
            wmma::fragment<wmma::matrix_a, 16, 16, 8, wmma::precision::tf32, wmma::row_major> af[4];
            wmma::fragment<wmma::matrix_b, 16, 16, 8, wmma::precision::tf32, wmma::col_major> bf[4];
#pragma unroll
            for (int i = 0; i < 4; i++)
                wmma::load_matrix_sync(af[i], &As[st][wm + i * 16][ks * 8], GPAD_);
#pragma unroll
            for (int j = 0; j < 4; j++)
                wmma::load_matrix_sync(bf[j], &Bs[st][wn + j * 16][ks * 8], GPAD_);
#pragma unroll
            for (int i = 0; i < 4; i++)
#pragma unroll
                for (int j = 0; j < 4; j++)
                    wmma::mma_sync(acc[i][j], af[i], bf[j], acc[i][j]);
        }
    }

#pragma unroll
    for (int i = 0; i < 4; i++)
#pragma unroll
        for (int j = 0; j < 4; j++)
            wmma::store_matrix_sync(
                Cm + (size_t)(m0 + wm + i * 16) * N + (n0 + wn + j * 16),
                acc[i][j], N, wmma::mem_row_major);
}

// ============================================================================
// RoPE + RMSNorm + head split (unchanged).
// ============================================================================
__global__ __launch_bounds__(64) void rope_rms(
    const float* __restrict__ qkv,
    float* __restrict__ Qo, float* __restrict__ Ko, float* __restrict__ Vo)
{
    const int h = blockIdx.x;
    const int t = blockIdx.y;
    const int b = blockIdx.z;
    const int i = threadIdx.x;

    const float* src = qkv + ((size_t)(b * T_ + t)) * NQKV_ + h * DH_;
    float x0 = src[2 * i];
    float x1 = src[2 * i + 1];

    if (h >= HQ_ + HKV_) {
        float* dst = Vo + ((size_t)(b * HKV_ + (h - HQ_ - HKV_)) * T_ + t) * DH_;
        dst[2 * i]     = x0;
        dst[2 * i + 1] = x1;
        return;
    }

    const float inv_freq = powf(10000.0f, -(float)i * (1.0f / 64.0f));
    const float ang = (float)t * inv_freq;
    float sn, cs;
    sincosf(ang, &sn, &cs);
    const float y0 = x0 * cs - x1 * sn;
    const float y1 = x1 * cs + x0 * sn;

    float ss = y0 * y0 + y1 * y1;
#pragma unroll
    for (int off = 16; off; off >>= 1)
        ss += __shfl_xor_sync(0xffffffffu, ss, off);
    __shared__ float sh[2];
    if ((i & 31) == 0) sh[i >> 5] = ss;
    __syncthreads();
    const float rn = rsqrtf((sh[0] + sh[1]) * (1.0f / 128.0f) + 1.1920929e-07f);

    float* dst = (h < HQ_)
        ? Qo + ((size_t)(b * HQ_ + h) * T_ + t) * DH_
        : Ko + ((size_t)(b * HKV_ + (h - HQ_)) * T_ + t) * DH_;
    dst[2 * i]     = y0 * rn;
    dst[2 * i + 1] = y1 * rn;
}

// ============================================================================
// Sliding-window flash attention, S and PV on wmma TF32 tensor cores
// (unchanged from R6).
// ============================================================================
#define AQL_ 132            // Q/K/V ld (pad 128+4)
#define APL_ 72             // S/P ld (pad 64+8)
#define ATTN_SMEM ((3 * 64 * AQL_ + 64 * APL_) * (int)sizeof(float))

__global__ __launch_bounds__(256) void attn_tc(
    const float* __restrict__ Qg, const float* __restrict__ Kg,
    const float* __restrict__ Vg, float* __restrict__ Yg)
{
    extern __shared__ __align__(16) float sm[];
    float* Qs = sm;                    // 64 x 132
    float* Ks = Qs + 64 * AQL_;        // 64 x 132 (reused as O staging)
    float* Vs = Ks + 64 * AQL_;        // 64 x 132
    float* Ps = Vs + 64 * AQL_;        // 64 x 72

    const int tid = threadIdx.x;
    const int tx  = tid & 15;
    const int ty  = tid >> 4;
    const int wid = tid >> 5;
    const int q0  = blockIdx.x << 6;
    const int h   = blockIdx.y;
    const int b   = blockIdx.z;
    const int hk  = h >> 2;

    const float* Qp = Qg + ((size_t)(b * HQ_ + h) * T_ + q0) * DH_;
    const float* Kp = Kg + ((size_t)(b * HKV_ + hk) * T_) * DH_;
    const float* Vp = Vg + ((size_t)(b * HKV_ + hk) * T_) * DH_;

    const float qsc = 0.08838834764831845f;  // 1/sqrt(128)
    for (int li = tid; li < 64 * 32; li += 256) {
        const int r  = li >> 5;
        const int c4 = (li & 31) << 2;
        float4 v = *(const float4*)(Qp + (size_t)r * DH_ + c4);
        float* d = Qs + r * AQL_ + c4;
        d[0] = wmma::__float_to_tf32(v.x * qsc);
        d[1] = wmma::__float_to_tf32(v.y * qsc);
        d[2] = wmma::__float_to_tf32(v.z * qsc);
        d[3] = wmma::__float_to_tf32(v.w * qsc);
    }

    float m_i[4], l_i[4], acc[4][8];
#pragma unroll
    for (int i = 0; i < 4; i++) {
        m_i[i] = -1e30f; l_i[i] = 0.f;
#pragma unroll
        for (int j = 0; j < 8; j++) acc[i][j] = 0.f;
    }

    int lo = q0 - (WIN_ - 1); if (lo < 0) lo = 0;
    const int kt0 = lo >> 6;
    const int kt1 = q0 >> 6;

    for (int kt = kt0; kt <= kt1; ++kt) {
        const int k0 = kt << 6;

        // ---- load K, V tiles (tf32-rounded) ----
        for (int li = tid; li < 64 * 32; li += 256) {
            const int r  = li >> 5;
            const int c4 = (li & 31) << 2;
            float4 kv = *(const float4*)(Kp + (size_t)(k0 + r) * DH_ + c4);
            float4 vv = *(const float4*)(Vp + (size_t)(k0 + r) * DH_ + c4);
            float* kd = Ks + r * AQL_ + c4;
            float* vd = Vs + r * AQL_ + c4;
            kd[0] = wmma::__float_to_tf32(kv.x);
            kd[1] = wmma::__float_to_tf32(kv.y);
            kd[2] = wmma::__float_to_tf32(kv.z);
            kd[3] = wmma::__float_to_tf32(kv.w);
            vd[0] = wmma::__float_to_tf32(vv.x);
            vd[1] = wmma::__float_to_tf32(vv.y);
            vd[2] = wmma::__float_to_tf32(vv.z);
            vd[3] = wmma::__float_to_tf32(vv.w);
        }
        __syncthreads();

        // ---- S = Q K^T via wmma: warp (wy, wx) does 32q x 16k ----
        {
            const int wy = wid & 1;
            const int wx = wid >> 1;
            wmma::fragment<wmma::accumulator, 16, 16, 8, float> sacc[2];
            wmma::fill_fragment(sacc[0], 0.0f);
            wmma::fill_fragment(sacc[1], 0.0f);
#pragma unroll
            for (int d = 0; d < DH_; d += 8) {
                wmma::fragment<wmma::matrix_a, 16, 16, 8, wmma::precision::tf32, wmma::row_major> af[2];
                wmma::fragment<wmma::matrix_b, 16, 16, 8, wmma::precision::tf32, wmma::col_major> bf;
                wmma::load_matrix_sync(af[0], Qs + (wy * 32 + 0)  * AQL_ + d, AQL_);
                wmma::load_matrix_sync(af[1], Qs + (wy * 32 + 16) * AQL_ + d, AQL_);
                wmma::load_matrix_sync(bf,    Ks + (wx * 16) * AQL_ + d, AQL_);
                wmma::mma_sync(sacc[0], af[0], bf, sacc[0]);
                wmma::mma_sync(sacc[1], af[1], bf, sacc[1]);
            }
            wmma::store_matrix_sync(Ps + (wy * 32 + 0)  * APL_ + wx * 16, sacc[0], APL_, wmma::mem_row_major);
            wmma::store_matrix_sync(Ps + (wy * 32 + 16) * APL_ + wx * 16, sacc[1], APL_, wmma::mem_row_major);
        }
        __syncthreads();

        // ---- softmax (SIMT): mask, online m/l update, write tf32 P ----
#pragma unroll
        for (int i = 0; i < 4; i++) {
            const int qi = q0 + ty * 4 + i;
            float* srow = Ps + (ty * 4 + i) * APL_ + (tx << 2);
            float s0 = srow[0], s1 = srow[1], s2 = srow[2], s3 = srow[3];
            const int kj = k0 + (tx << 2);
            s0 = (qi >= kj + 0 && (qi - kj - 0) < WIN_) ? s0 : -1e30f;
            s1 = (qi >= kj + 1 && (qi - kj - 1) < WIN_) ? s1 : -1e30f;
            s2 = (qi >= kj + 2 && (qi - kj - 2) < WIN_) ? s2 : -1e30f;
            s3 = (qi >= kj + 3 && (qi - kj - 3) < WIN_) ? s3 : -1e30f;
            float rmax = fmaxf(fmaxf(s0, s1), fmaxf(s2, s3));
#pragma unroll
            for (int off = 8; off; off >>= 1)
                rmax = fmaxf(rmax, __shfl_xor_sync(0xffffffffu, rmax, off));
            const float mn = fmaxf(m_i[i], rmax);

            float p0 = __expf(s0 - mn), p1 = __expf(s1 - mn);
            float p2 = __expf(s2 - mn), p3 = __expf(s3 - mn);
            float rs = p0 + p1 + p2 + p3;
#pragma unroll
            for (int off = 8; off; off >>= 1)
                rs += __shfl_xor_sync(0xffffffffu, rs, off);

            const float sc = __expf(m_i[i] - mn);
            l_i[i] = l_i[i] * sc + rs;
            m_i[i] = mn;
#pragma unroll
            for (int j = 0; j < 8; j++) acc[i][j] *= sc;

            srow[0] = wmma::__float_to_tf32(p0);
            srow[1] = wmma::__float_to_tf32(p1);
            srow[2] = wmma::__float_to_tf32(p2);
            srow[3] = wmma::__float_to_tf32(p3);
        }
        __syncthreads();

        // ---- O_tile = P V via wmma: warp (wm, wn) does 32q x 32d -> Ks ----
        {
            const int wm = (wid & 1) * 32;
            const int wn = (wid >> 1) * 32;
            wmma::fragment<wmma::accumulator, 16, 16, 8, float> oacc[2][2];
#pragma unroll
            for (int i = 0; i < 2; i++)
#pragma unroll
                for (int j = 0; j < 2; j++)
                    wmma::fill_fragment(oacc[i][j], 0.0f);
#pragma unroll
            for (int k = 0; k < 64; k += 8) {
                wmma::fragment<wmma::matrix_a, 16, 16, 8, wmma::precision::tf32, wmma::row_major> af[2];
                wmma::fragment<wmma::matrix_b, 16, 16, 8, wmma::precision::tf32, wmma::row_major> bf[2];
                wmma::load_matrix_sync(af[0], Ps + (wm + 0)  * APL_ + k, APL_);
                wmma::load_matrix_sync(af[1], Ps + (wm + 16) * APL_ + k, APL_);
                wmma::load_matrix_sync(bf[0], Vs + k * AQL_ + wn + 0,  AQL_);
                wmma::load_matrix_sync(bf[1], Vs + k * AQL_ + wn + 16, AQL_);
#pragma unroll
                for (int i = 0; i < 2; i++)
#pragma unroll
                    for (int j = 0; j < 2; j++)
                        wmma::mma_sync(oacc[i][j], af[i], bf[j], oacc[i][j]);
            }
#pragma unroll
            for (int i = 0; i < 2; i++)
#pragma unroll
                for (int j = 0; j < 2; j++)
                    wmma::store_matrix_sync(
                        Ks + (wm + i * 16) * AQL_ + wn + j * 16,
                        oacc[i][j], AQL_, wmma::mem_row_major);
        }
        __syncthreads();

        // ---- merge staged O tile into SIMT accumulators ----
#pragma unroll
        for (int i = 0; i < 4; i++) {
            const float* orow = Ks + (ty * 4 + i) * AQL_ + (tx << 3);
#pragma unroll
            for (int j = 0; j < 8; j++) acc[i][j] += orow[j];
        }
        __syncthreads();   // Ks reloaded next iteration
    }

    // epilogue: y = acc / l, rounded to tf32 (feeds the proj GEMM directly)
#pragma unroll
    for (int i = 0; i < 4; i++) {
        const float inv = 1.0f / l_i[i];
        const int t = q0 + ty * 4 + i;
        float* yp = Yg + ((size_t)(b * T_ + t)) * C_ + h * DH_ + (tx << 3);
        *(float4*)yp = make_float4(
            wmma::__float_to_tf32(acc[i][0] * inv), wmma::__float_to_tf32(acc[i][1] * inv),
            wmma::__float_to_tf32(acc[i][2] * inv), wmma::__float_to_tf32(acc[i][3] * inv));
        *(float4*)(yp + 4) = make_float4(
            wmma::__float_to_tf32(acc[i][4] * inv), wmma::__float_to_tf32(acc[i][5] * inv),
            wmma::__float_to_tf32(acc[i][6] * inv), wmma::__float_to_tf32(acc[i][7] * inv));
    }
}

// ============================================================================
// launch
// ============================================================================
extern "C" void kernel_launch(void* const* d_in, const int* in_sizes, int n_in,
                              void* d_out, int out_size)
{
    const float* x      = (const float*)d_in[0];
    const float* w_qkv  = (const float*)d_in[1];
    const float* w_proj = (const float*)d_in[2];
    float* out = (float*)d_out;

    float *p_qkv, *p_Q, *p_K, *p_V, *p_y, *p_xr, *p_wq, *p_wp;
    cudaGetSymbolAddress((void**)&p_qkv, g_qkv);
    cudaGetSymbolAddress((void**)&p_Q,   g_Q);
    cudaGetSymbolAddress((void**)&p_K,   g_K);
    cudaGetSymbolAddress((void**)&p_V,   g_V);
    cudaGetSymbolAddress((void**)&p_y,   g_y);
    cudaGetSymbolAddress((void**)&p_xr,  g_xr);
    cudaGetSymbolAddress((void**)&p_wq,  g_wq);
    cudaGetSymbolAddress((void**)&p_wp,  g_wp);

    cudaFuncSetAttribute(gemm_tf32, cudaFuncAttributeMaxDynamicSharedMemorySize, GEMM_SMEM);
    cudaFuncSetAttribute(attn_tc, cudaFuncAttributeMaxDynamicSharedMemorySize, ATTN_SMEM);

    // 0) round GEMM inputs to tf32 (RNE)
    round_tf32<<<(MTOK_ * C_ / 4 + 255) / 256, 256>>>(x, p_xr, MTOK_ * C_ / 4);
    round_tf32<<<(NQKV_ * C_ / 4 + 255) / 256, 256>>>(w_qkv, p_wq, NQKV_ * C_ / 4);
    round_tf32<<<(C_ * C_ / 4 + 255) / 256, 256>>>(w_proj, p_wp, C_ * C_ / 4);

    // 1) qkv = x @ w_qkv^T
    gemm_tf32<<<dim3(NQKV_ / BN_, MTOK_ / BM_), 256, GEMM_SMEM>>>(
        p_xr, p_wq, p_qkv, MTOK_, NQKV_, C_);

    // 2) RoPE + RMSNorm + split
    rope_rms<<<dim3(HQ_ + 2 * HKV_, T_, B_), 64>>>(p_qkv, p_Q, p_K, p_V);

    // 3) attention (tensor-core S/PV); y written tf32-rounded
    attn_tc<<<dim3(T_ / 64, HQ_, B_), 256, ATTN_SMEM>>>(p_Q, p_K, p_V, p_y);

    // 4) out = y @ w_proj^T
    gemm_tf32<<<dim3(C_ / BN_, MTOK_ / BM_), 256, GEMM_SMEM>>>(
        p_y, p_wp, out, MTOK_, C_, C_);
}

// round 8
// speedup vs baseline: 4.6907x; 3.0421x over previous
#include <cuda_runtime.h>
#include <cstdint>
#include <math.h>
#include <mma.h>
#include <cuda_fp16.h>

using namespace nvcuda;

#define B_    2
#define T_    2048
#define C_    2048
#define HQ_   16
#define HKV_  4
#define DH_   128
#define WIN_  512
#define NQKV_ 3072          // (HQ + 2*HKV) * DH
#define MTOK_ 4096          // B * T

// ---------------- scratch (static __device__, no allocations) ----------------
__device__ float  g_qkv[MTOK_ * NQKV_];            // fp32 qkv (pre-rope)
__device__ __half g_Qh[B_ * HQ_ * T_ * DH_];       // fp16, pre-scaled by 1/sqrt(d)
__device__ __half g_Kh[B_ * HKV_ * T_ * DH_];
__device__ __half g_Vh[B_ * HKV_ * T_ * DH_];
__device__ __half g_yh[MTOK_ * C_];                // fp16 attention output
__device__ __half g_xh[MTOK_ * C_];                // fp16 x
__device__ __half g_wqh[NQKV_ * C_];               // fp16 w_qkv
__device__ __half g_wph[C_ * C_];                  // fp16 w_proj

// ============================================================================
// fp32 -> fp16 (RNE) conversion
// ============================================================================
__global__ __launch_bounds__(256) void to_half(
    const float* __restrict__ in, __half* __restrict__ out, int n4)
{
    const int i = blockIdx.x * blockDim.x + threadIdx.x;
    if (i >= n4) return;
    float4 v = ((const float4*)in)[i];
    __half2* o = (__half2*)out;
    o[2 * i]     = __floats2half2_rn(v.x, v.y);
    o[2 * i + 1] = __floats2half2_rn(v.z, v.w);
}

// ============================================================================
// FP16 tensor-core GEMM:  C[M,N] = A[M,K] @ B[N,K]^T  (row-major, K contig)
// CTA tile 128x256, BK=32, 3-stage cp.async, 8 warps 2(m) x 4(n),
// warp tile 64x64 = 4x4 wmma m16n16k16 fragments, fp32 accumulate.
// ============================================================================
#define BM_   128
#define BN_   256
#define GBK_  32
#define GLD_  40          // halfs per row (32 + 8 pad); 80B, 16B-multiple
#define GS_   3
#define GEMM_SMEM (GS_ * (BM_ + BN_) * GLD_ * (int)sizeof(__half))

__device__ __forceinline__ void cp_async16(void* smem_dst, const void* gsrc) {
    unsigned int d = (unsigned int)__cvta_generic_to_shared(smem_dst);
    asm volatile("cp.async.cg.shared.global [%0], [%1], 16;\n" :: "r"(d), "l"(gsrc));
}

__global__ __launch_bounds__(256, 1) void gemm_fp16(
    const __half* __restrict__ A, const __half* __restrict__ Bm,
    float* __restrict__ Cm, int M, int N, int K)
{
    extern __shared__ __align__(16) __half hsm[];
    __half (*As)[BM_][GLD_] = (__half (*)[BM_][GLD_])hsm;
    __half (*Bs)[BN_][GLD_] = (__half (*)[BN_][GLD_])(hsm + GS_ * BM_ * GLD_);

    const int tid = threadIdx.x;
    const int wid = tid >> 5;
    const int m0  = blockIdx.y * BM_;
    const int n0  = blockIdx.x * BN_;
    const int wm  = (wid & 1) * 64;
    const int wn  = (wid >> 1) * 64;

    // load mapping: 32 halfs/row = 4 x 8-half chunks; 256 thr cover 64 rows
    const int lr = tid >> 2;            // 0..63
    const int lc = (tid & 3) << 3;      // 0,8,16,24

    const __half* Abase = A  + (size_t)(m0 + lr) * K + lc;
    const __half* Bbase = Bm + (size_t)(n0 + lr) * K + lc;
    const size_t rowK64 = (size_t)64 * K;

    wmma::fragment<wmma::accumulator, 16, 16, 16, float> acc[4][4];
#pragma unroll
    for (int i = 0; i < 4; i++)
#pragma unroll
        for (int j = 0; j < 4; j++)
            wmma::fill_fragment(acc[i][j], 0.0f);

    const int KT = K / GBK_;

#pragma unroll
    for (int s = 0; s < GS_ - 1; ++s) {
        const size_t ko = (size_t)s * GBK_;
        cp_async16(&As[s][lr][lc],       Abase + ko);
        cp_async16(&As[s][lr + 64][lc],  Abase + ko + rowK64);
        cp_async16(&Bs[s][lr][lc],       Bbase + ko);
        cp_async16(&Bs[s][lr + 64][lc],  Bbase + ko + rowK64);
        cp_async16(&Bs[s][lr + 128][lc], Bbase + ko + 2 * rowK64);
        cp_async16(&Bs[s][lr + 192][lc], Bbase + ko + 3 * rowK64);
        asm volatile("cp.async.commit_group;\n" ::);
    }

    for (int kt = 0; kt < KT; ++kt) {
        asm volatile("cp.async.wait_group %0;\n" :: "n"(GS_ - 2));
        __syncthreads();

        if (kt + GS_ - 1 < KT) {
            const int ws = (kt + GS_ - 1) % GS_;
            const size_t ko = (size_t)(kt + GS_ - 1) * GBK_;
            cp_async16(&As[ws][lr][lc],       Abase + ko);
            cp_async16(&As[ws][lr + 64][lc],  Abase + ko + rowK64);
            cp_async16(&Bs[ws][lr][lc],       Bbase + ko);
            cp_async16(&Bs[ws][lr + 64][lc],  Bbase + ko + rowK64);
            cp_async16(&Bs[ws][lr + 128][lc], Bbase + ko + 2 * rowK64);
            cp_async16(&Bs[ws][lr + 192][lc], Bbase + ko + 3 * rowK64);
        }
        asm volatile("cp.async.commit_group;\n" ::);

        const int st = kt % GS_;
#pragma unroll
        for (int ks = 0; ks < 2; ++ks) {
            wmma::fragment<wmma::matrix_a, 16, 16, 16, half, wmma::row_major> af[4];
            wmma::fragment<wmma::matrix_b, 16, 16, 16, half, wmma::col_major> bf[4];
#pragma unroll
            for (int i = 0; i < 4; i++)
                wmma::load_matrix_sync(af[i], &As[st][wm + i * 16][ks * 16], GLD_);
#pragma unroll
            for (int j = 0; j < 4; j++)
                wmma::load_matrix_sync(bf[j], &Bs[st][wn + j * 16][ks * 16], GLD_);
#pragma unroll
            for (int i = 0; i < 4; i++)
#pragma unroll
                for (int j = 0; j < 4; j++)
                    wmma::mma_sync(acc[i][j], af[i], bf[j], acc[i][j]);
        }
    }

#pragma unroll
    for (int i = 0; i < 4; i++)
#pragma unroll
        for (int j = 0; j < 4; j++)
            wmma::store_matrix_sync(
                Cm + (size_t)(m0 + wm + i * 16) * N + (n0 + wn + j * 16),
                acc[i][j], N, wmma::mem_row_major);
}

// ============================================================================
// RoPE + RMSNorm + head split; outputs fp16.  Q is pre-scaled by 1/sqrt(d).
// ============================================================================
__global__ __launch_bounds__(64) void rope_rms(
    const float* __restrict__ qkv,
    __half* __restrict__ Qo, __half* __restrict__ Ko, __half* __restrict__ Vo)
{
    const int h = blockIdx.x;
    const int t = blockIdx.y;
    const int b = blockIdx.z;
    const int i = threadIdx.x;      // 0..63

    const float* src = qkv + ((size_t)(b * T_ + t)) * NQKV_ + h * DH_;
    float x0 = src[2 * i];
    float x1 = src[2 * i + 1];

    if (h >= HQ_ + HKV_) {          // V heads: convert only
        __half2* dst = (__half2*)(Vo +
            ((size_t)(b * HKV_ + (h - HQ_ - HKV_)) * T_ + t) * DH_);
        dst[i] = __floats2half2_rn(x0, x1);
        return;
    }

    const float inv_freq = powf(10000.0f, -(float)i * (1.0f / 64.0f));
    const float ang = (float)t * inv_freq;
    float sn, cs;
    sincosf(ang, &sn, &cs);
    const float y0 = x0 * cs - x1 * sn;
    const float y1 = x1 * cs + x0 * sn;

    float ss = y0 * y0 + y1 * y1;
#pragma unroll
    for (int off = 16; off; off >>= 1)
        ss += __shfl_xor_sync(0xffffffffu, ss, off);
    __shared__ float sh[2];
    if ((i & 31) == 0) sh[i >> 5] = ss;
    __syncthreads();
    float rn = rsqrtf((sh[0] + sh[1]) * (1.0f / 128.0f) + 1.1920929e-07f);

    if (h < HQ_) {
        rn *= 0.08838834764831845f;   // fold 1/sqrt(128) into Q
        __half2* dst = (__half2*)(Qo + ((size_t)(b * HQ_ + h) * T_ + t) * DH_);
        dst[i] = __floats2half2_rn(y0 * rn, y1 * rn);
    } else {
        __half2* dst = (__half2*)(Ko + ((size_t)(b * HKV_ + (h - HQ_)) * T_ + t) * DH_);
        dst[i] = __floats2half2_rn(y0 * rn, y1 * rn);
    }
}

// ============================================================================
// Sliding-window flash attention, fp16 wmma S and PV, fp32 accumulate.
// Tile 64q x 64k, DH=128, 256 threads = 8 warps.
// ============================================================================
#define QL_ 136             // half ld for Q/K/V tiles (128 + 8)
#define PL_ 72              // half ld for P tile (64 + 8)
#define OL_ 132             // float ld for S/O staging (128 + 4)
#define ATTN_SMEM (64 * OL_ * (int)sizeof(float) + \
                   (3 * 64 * QL_ + 64 * PL_) * (int)sizeof(__half))

__global__ __launch_bounds__(256) void attn_tc(
    const __half* __restrict__ Qg, const __half* __restrict__ Kg,
    const __half* __restrict__ Vg, __half* __restrict__ Yg)
{
    extern __shared__ __align__(16) char asm_[];
    float*  Osf = (float*)asm_;                      // 64 x 132 fp32 staging
    __half* Qsh = (__half*)(Osf + 64 * OL_);         // 64 x 136
    __half* Ksh = Qsh + 64 * QL_;                    // 64 x 136
    __half* Vsh = Ksh + 64 * QL_;                    // 64 x 136
    __half* Psh = Vsh + 64 * QL_;                    // 64 x 72

    const int tid = threadIdx.x;
    const int tx  = tid & 15;
    const int ty  = tid >> 4;
    const int wid = tid >> 5;
    const int q0  = blockIdx.x << 6;
    const int h   = blockIdx.y;
    const int b   = blockIdx.z;
    const int hk  = h >> 2;

    const __half* Qp = Qg + ((size_t)(b * HQ_ + h) * T_ + q0) * DH_;
    const __half* Kp = Kg + ((size_t)(b * HKV_ + hk) * T_) * DH_;
    const __half* Vp = Vg + ((size_t)(b * HKV_ + hk) * T_) * DH_;

    // Q tile: pure 16B copies (Q already scaled + fp16)
    for (int li = tid; li < 64 * 16; li += 256) {
        const int r  = li >> 4;
        const int c8 = (li & 15) << 3;
        *(uint4*)(Qsh + r * QL_ + c8) = *(const uint4*)(Qp + (size_t)r * DH_ + c8);
    }

    float m_i[4], l_i[4], acc[4][8];
#pragma unroll
    for (int i = 0; i < 4; i++) {
        m_i[i] = -1e30f; l_i[i] = 0.f;
#pragma unroll
        for (int j = 0; j < 8; j++) acc[i][j] = 0.f;
    }

    int lo = q0 - (WIN_ - 1); if (lo < 0) lo = 0;
    const int kt0 = lo >> 6;
    const int kt1 = q0 >> 6;

    for (int kt = kt0; kt <= kt1; ++kt) {
        const int k0 = kt << 6;

        // ---- load K, V tiles (16B copies) ----
        for (int li = tid; li < 64 * 16; li += 256) {
            const int r  = li >> 4;
            const int c8 = (li & 15) << 3;
            *(uint4*)(Ksh + r * QL_ + c8) =
                *(const uint4*)(Kp + (size_t)(k0 + r) * DH_ + c8);
            *(uint4*)(Vsh + r * QL_ + c8) =
                *(const uint4*)(Vp + (size_t)(k0 + r) * DH_ + c8);
        }
        __syncthreads();

        // ---- S = Q K^T: warp (wy, wx) does 32q x 16k, fp32 acc -> Osf ----
        {
            const int wy = wid & 1;
            const int wx = wid >> 1;
            wmma::fragment<wmma::accumulator, 16, 16, 16, float> sacc[2];
            wmma::fill_fragment(sacc[0], 0.0f);
            wmma::fill_fragment(sacc[1], 0.0f);
#pragma unroll
            for (int d = 0; d < DH_; d += 16) {
                wmma::fragment<wmma::matrix_a, 16, 16, 16, half, wmma::row_major> af[2];
                wmma::fragment<wmma::matrix_b, 16, 16, 16, half, wmma::col_major> bf;
                wmma::load_matrix_sync(af[0], Qsh + (wy * 32 + 0)  * QL_ + d, QL_);
                wmma::load_matrix_sync(af[1], Qsh + (wy * 32 + 16) * QL_ + d, QL_);
                wmma::load_matrix_sync(bf,    Ksh + (wx * 16) * QL_ + d, QL_);
                wmma::mma_sync(sacc[0], af[0], bf, sacc[0]);
                wmma::mma_sync(sacc[1], af[1], bf, sacc[1]);
            }
            wmma::store_matrix_sync(Osf + (wy * 32 + 0)  * OL_ + wx * 16, sacc[0], OL_, wmma::mem_row_major);
            wmma::store_matrix_sync(Osf + (wy * 32 + 16) * OL_ + wx * 16, sacc[1], OL_, wmma::mem_row_major);
        }
        __syncthreads();

        // ---- softmax (SIMT): mask, online m/l update, write fp16 P ----
#pragma unroll
        for (int i = 0; i < 4; i++) {
            const int qi = q0 + ty * 4 + i;
            const float* srow = Osf + (ty * 4 + i) * OL_ + (tx << 2);
            float s0 = srow[0], s1 = srow[1], s2 = srow[2], s3 = srow[3];
            const int kj = k0 + (tx << 2);
            s0 = (qi >= kj + 0 && (qi - kj - 0) < WIN_) ? s0 : -1e30f;
            s1 = (qi >= kj + 1 && (qi - kj - 1) < WIN_) ? s1 : -1e30f;
            s2 = (qi >= kj + 2 && (qi - kj - 2) < WIN_) ? s2 : -1e30f;
            s3 = (qi >= kj + 3 && (qi - kj - 3) < WIN_) ? s3 : -1e30f;
            float rmax = fmaxf(fmaxf(s0, s1), fmaxf(s2, s3));
#pragma unroll
            for (int off = 8; off; off >>= 1)
                rmax = fmaxf(rmax, __shfl_xor_sync(0xffffffffu, rmax, off));
            const float mn = fmaxf(m_i[i], rmax);

            float p0 = __expf(s0 - mn), p1 = __expf(s1 - mn);
            float p2 = __expf(s2 - mn), p3 = __expf(s3 - mn);
            float rs = p0 + p1 + p2 + p3;
#pragma unroll
            for (int off = 8; off; off >>= 1)
                rs += __shfl_xor_sync(0xffffffffu, rs, off);

            const float sc = __expf(m_i[i] - mn);
            l_i[i] = l_i[i] * sc + rs;
            m_i[i] = mn;
#pragma unroll
            for (int j = 0; j < 8; j++) acc[i][j] *= sc;

            __half2* prow = (__half2*)(Psh + (ty * 4 + i) * PL_ + (tx << 2));
            prow[0] = __floats2half2_rn(p0, p1);
            prow[1] = __floats2half2_rn(p2, p3);
        }
        __syncthreads();

        // ---- O_tile = P V: warp (wm, wn) does 32q x 32d -> Osf ----
        {
            const int wm = (wid & 1) * 32;
            const int wn = (wid >> 1) * 32;
            wmma::fragment<wmma::accumulator, 16, 16, 16, float> oacc[2][2];
#pragma unroll
            for (int i = 0; i < 2; i++)
#pragma unroll
                for (int j = 0; j < 2; j++)
                    wmma::fill_fragment(oacc[i][j], 0.0f);
#pragma unroll
            for (int k = 0; k < 64; k += 16) {
                wmma::fragment<wmma::matrix_a, 16, 16, 16, half, wmma::row_major> af[2];
                wmma::fragment<wmma::matrix_b, 16, 16, 16, half, wmma::row_major> bf[2];
                wmma::load_matrix_sync(af[0], Psh + (wm + 0)  * PL_ + k, PL_);
                wmma::load_matrix_sync(af[1], Psh + (wm + 16) * PL_ + k, PL_);
                wmma::load_matrix_sync(bf[0], Vsh + k * QL_ + wn + 0,  QL_);
                wmma::load_matrix_sync(bf[1], Vsh + k * QL_ + wn + 16, QL_);
#pragma unroll
                for (int i = 0; i < 2; i++)
#pragma unroll
                    for (int j = 0; j < 2; j++)
                        wmma::mma_sync(oacc[i][j], af[i], bf[j], oacc[i][j]);
            }
#pragma unroll
            for (int i = 0; i < 2; i++)
#pragma unroll
                for (int j = 0; j < 2; j++)
                    wmma::store_matrix_sync(
                        Osf + (wm + i * 16) * OL_ + wn + j * 16,
                        oacc[i][j], OL_, wmma::mem_row_major);
        }
        __syncthreads();

        // ---- merge staged O tile into SIMT accumulators ----
#pragma unroll
        for (int i = 0; i < 4; i++) {
            const float* orow = Osf + (ty * 4 + i) * OL_ + (tx << 3);
#pragma unroll
            for (int j = 0; j < 8; j++) acc[i][j] += orow[j];
        }
        __syncthreads();   // Osf/Ksh/Vsh rewritten next iteration
    }

    // epilogue: y = acc / l, fp16 (feeds the proj GEMM directly)
#pragma unroll
    for (int i = 0; i < 4; i++) {
        const float inv = 1.0f / l_i[i];
        const int t = q0 + ty * 4 + i;
        __half2 o[4];
#pragma unroll
        for (int j = 0; j < 4; j++)
            o[j] = __floats2half2_rn(acc[i][2 * j] * inv, acc[i][2 * j + 1] * inv);
        *(uint4*)(Yg + ((size_t)(b * T_ + t)) * C_ + h * DH_ + (tx << 3)) =
            *(uint4*)o;
    }
}

// ============================================================================
// launch
// ============================================================================
extern "C" void kernel_launch(void* const* d_in, const int* in_sizes, int n_in,
                              void* d_out, int out_size)
{
    const float* x      = (const float*)d_in[0];
    const float* w_qkv  = (const float*)d_in[1];
    const float* w_proj = (const float*)d_in[2];
    float* out = (float*)d_out;

    float *p_qkv;
    __half *p_Qh, *p_Kh, *p_Vh, *p_yh, *p_xh, *p_wqh, *p_wph;
    cudaGetSymbolAddress((void**)&p_qkv, g_qkv);
    cudaGetSymbolAddress((void**)&p_Qh,  g_Qh);
    cudaGetSymbolAddress((void**)&p_Kh,  g_Kh);
    cudaGetSymbolAddress((void**)&p_Vh,  g_Vh);
    cudaGetSymbolAddress((void**)&p_yh,  g_yh);
    cudaGetSymbolAddress((void**)&p_xh,  g_xh);
    cudaGetSymbolAddress((void**)&p_wqh, g_wqh);
    cudaGetSymbolAddress((void**)&p_wph, g_wph);

    cudaFuncSetAttribute(gemm_fp16, cudaFuncAttributeMaxDynamicSharedMemorySize, GEMM_SMEM);
    cudaFuncSetAttribute(attn_tc, cudaFuncAttributeMaxDynamicSharedMemorySize, ATTN_SMEM);

    // 0) convert GEMM inputs to fp16 (RNE)
    to_half<<<(MTOK_ * C_ / 4 + 255) / 256, 256>>>(x, p_xh, MTOK_ * C_ / 4);
    to_half<<<(NQKV_ * C_ / 4 + 255) / 256, 256>>>(w_qkv, p_wqh, NQKV_ * C_ / 4);
    to_half<<<(C_ * C_ / 4 + 255) / 256, 256>>>(w_proj, p_wph, C_ * C_ / 4);

    // 1) qkv = x @ w_qkv^T   (fp16 HMMA, fp32 accum)
    gemm_fp16<<<dim3(NQKV_ / BN_, MTOK_ / BM_), 256, GEMM_SMEM>>>(
        p_xh, p_wqh, p_qkv, MTOK_, NQKV_, C_);

    // 2) RoPE + RMSNorm + split; Q/K/V emitted fp16 (Q pre-scaled)
    rope_rms<<<dim3(HQ_ + 2 * HKV_, T_, B_), 64>>>(p_qkv, p_Qh, p_Kh, p_Vh);

    // 3) attention (fp16 tensor cores); y written fp16
    attn_tc<<<dim3(T_ / 64, HQ_, B_), 256, ATTN_SMEM>>>(p_Qh, p_Kh, p_Vh, p_yh);

    // 4) out = y @ w_proj^T  (fp16 HMMA, fp32 accum)
    gemm_fp16<<<dim3(C_ / BN_, MTOK_ / BM_), 256, GEMM_SMEM>>>(
        p_yh, p_wph, out, MTOK_, C_, C_);
}

// round 9
// speedup vs baseline: 4.9560x; 1.0566x over previous
#include <cuda_runtime.h>
#include <cstdint>
#include <math.h>
#include <mma.h>
#include <cuda_fp16.h>

using namespace nvcuda;

#define B_    2
#define T_    2048
#define C_    2048
#define HQ_   16
#define HKV_  4
#define DH_   128
#define WIN_  512
#define NQKV_ 3072          // (HQ + 2*HKV) * DH
#define MTOK_ 4096          // B * T

// ---------------- scratch (static __device__, no allocations) ----------------
__device__ float  g_qkv[MTOK_ * NQKV_];            // fp32 qkv (pre-rope)
__device__ __half g_Qh[B_ * HQ_ * T_ * DH_];       // fp16, pre-scaled by 1/sqrt(d)
__device__ __half g_Kh[B_ * HKV_ * T_ * DH_];
__device__ __half g_Vh[B_ * HKV_ * T_ * DH_];
__device__ __half g_yh[MTOK_ * C_];                // fp16 attention output
__device__ __half g_xh[MTOK_ * C_];                // fp16 x
__device__ __half g_wqh[NQKV_ * C_];               // fp16 w_qkv
__device__ __half g_wph[C_ * C_];                  // fp16 w_proj

// ============================================================================
// fp32 -> fp16 (RNE) conversion
// ============================================================================
__global__ __launch_bounds__(256) void to_half(
    const float* __restrict__ in, __half* __restrict__ out, int n4)
{
    const int i = blockIdx.x * blockDim.x + threadIdx.x;
    if (i >= n4) return;
    float4 v = ((const float4*)in)[i];
    __half2* o = (__half2*)out;
    o[2 * i]     = __floats2half2_rn(v.x, v.y);
    o[2 * i + 1] = __floats2half2_rn(v.z, v.w);
}

// ============================================================================
// FP16 tensor-core GEMM:  C[M,N] = A[M,K] @ B[N,K]^T  (row-major, K contig)
// CTA tile 128x128, BK=32, 3-stage cp.async, 8 warps 2(m) x 4(n),
// warp tile 64x32, fp32 accumulate.  __launch_bounds__(256,2) caps regs at
// 128 so TWO CTAs co-reside per SM — sync/wait stalls in one CTA are hidden
// by the other's MMAs (R4..R8 showed tile size doesn't move tensor%, 1-CTA
// latency exposure does).
// ============================================================================
#define BM_   128
#define BN_   128
#define GBK_  32
#define GLD_  40          // halfs per row (32 + 8 pad); 80B, 16B-multiple
#define GS_   3
#define GEMM_SMEM (GS_ * (BM_ + BN_) * GLD_ * (int)sizeof(__half))

__device__ __forceinline__ void cp_async16(void* smem_dst, const void* gsrc) {
    unsigned int d = (unsigned int)__cvta_generic_to_shared(smem_dst);
    asm volatile("cp.async.cg.shared.global [%0], [%1], 16;\n" :: "r"(d), "l"(gsrc));
}

__global__ __launch_bounds__(256, 2) void gemm_fp16(
    const __half* __restrict__ A, const __half* __restrict__ Bm,
    float* __restrict__ Cm, int M, int N, int K)
{
    extern __shared__ __align__(16) __half hsm[];
    __half (*As)[BM_][GLD_] = (__half (*)[BM_][GLD_])hsm;
    __half (*Bs)[BN_][GLD_] = (__half (*)[BN_][GLD_])(hsm + GS_ * BM_ * GLD_);

    const int tid = threadIdx.x;
    const int wid = tid >> 5;
    const int m0  = blockIdx.y * BM_;
    const int n0  = blockIdx.x * BN_;
    const int wm  = (wid & 1) * 64;     // 2 warps over 128 m
    const int wn  = (wid >> 1) * 32;    // 4 warps over 128 n

    // load mapping: 32 halfs/row = 4 x 8-half chunks; 256 thr cover 64 rows
    const int lr = tid >> 2;            // 0..63
    const int lc = (tid & 3) << 3;      // 0,8,16,24

    const __half* Abase = A  + (size_t)(m0 + lr) * K + lc;
    const __half* Bbase = Bm + (size_t)(n0 + lr) * K + lc;
    const size_t rowK64 = (size_t)64 * K;

    wmma::fragment<wmma::accumulator, 16, 16, 16, float> acc[4][2];
#pragma unroll
    for (int i = 0; i < 4; i++)
#pragma unroll
        for (int j = 0; j < 2; j++)
            wmma::fill_fragment(acc[i][j], 0.0f);

    const int KT = K / GBK_;

#pragma unroll
    for (int s = 0; s < GS_ - 1; ++s) {
        const size_t ko = (size_t)s * GBK_;
        cp_async16(&As[s][lr][lc],      Abase + ko);
        cp_async16(&As[s][lr + 64][lc], Abase + ko + rowK64);
        cp_async16(&Bs[s][lr][lc],      Bbase + ko);
        cp_async16(&Bs[s][lr + 64][lc], Bbase + ko + rowK64);
        asm volatile("cp.async.commit_group;\n" ::);
    }

    for (int kt = 0; kt < KT; ++kt) {
        asm volatile("cp.async.wait_group %0;\n" :: "n"(GS_ - 2));
        __syncthreads();

        if (kt + GS_ - 1 < KT) {
            const int ws = (kt + GS_ - 1) % GS_;
            const size_t ko = (size_t)(kt + GS_ - 1) * GBK_;
            cp_async16(&As[ws][lr][lc],      Abase + ko);
            cp_async16(&As[ws][lr + 64][lc], Abase + ko + rowK64);
            cp_async16(&Bs[ws][lr][lc],      Bbase + ko);
            cp_async16(&Bs[ws][lr + 64][lc], Bbase + ko + rowK64);
        }
        asm volatile("cp.async.commit_group;\n" ::);

        const int st = kt % GS_;
#pragma unroll
        for (int ks = 0; ks < 2; ++ks) {
            wmma::fragment<wmma::matrix_a, 16, 16, 16, half, wmma::row_major> af[4];
            wmma::fragment<wmma::matrix_b, 16, 16, 16, half, wmma::col_major> bf[2];
#pragma unroll
            for (int i = 0; i < 4; i++)
                wmma::load_matrix_sync(af[i], &As[st][wm + i * 16][ks * 16], GLD_);
#pragma unroll
            for (int j = 0; j < 2; j++)
                wmma::load_matrix_sync(bf[j], &Bs[st][wn + j * 16][ks * 16], GLD_);
#pragma unroll
            for (int i = 0; i < 4; i++)
#pragma unroll
                for (int j = 0; j < 2; j++)
                    wmma::mma_sync(acc[i][j], af[i], bf[j], acc[i][j]);
        }
    }

#pragma unroll
    for (int i = 0; i < 4; i++)
#pragma unroll
        for (int j = 0; j < 2; j++)
            wmma::store_matrix_sync(
                Cm + (size_t)(m0 + wm + i * 16) * N + (n0 + wn + j * 16),
                acc[i][j], N, wmma::mem_row_major);
}

// ============================================================================
// RoPE + RMSNorm + head split; outputs fp16.  Q is pre-scaled by 1/sqrt(d).
// ============================================================================
__global__ __launch_bounds__(64) void rope_rms(
    const float* __restrict__ qkv,
    __half* __restrict__ Qo, __half* __restrict__ Ko, __half* __restrict__ Vo)
{
    const int h = blockIdx.x;
    const int t = blockIdx.y;
    const int b = blockIdx.z;
    const int i = threadIdx.x;      // 0..63

    const float* src = qkv + ((size_t)(b * T_ + t)) * NQKV_ + h * DH_;
    float x0 = src[2 * i];
    float x1 = src[2 * i + 1];

    if (h >= HQ_ + HKV_) {          // V heads: convert only
        __half2* dst = (__half2*)(Vo +
            ((size_t)(b * HKV_ + (h - HQ_ - HKV_)) * T_ + t) * DH_);
        dst[i] = __floats2half2_rn(x0, x1);
        return;
    }

    const float inv_freq = powf(10000.0f, -(float)i * (1.0f / 64.0f));
    const float ang = (float)t * inv_freq;
    float sn, cs;
    sincosf(ang, &sn, &cs);
    const float y0 = x0 * cs - x1 * sn;
    const float y1 = x1 * cs + x0 * sn;

    float ss = y0 * y0 + y1 * y1;
#pragma unroll
    for (int off = 16; off; off >>= 1)
        ss += __shfl_xor_sync(0xffffffffu, ss, off);
    __shared__ float sh[2];
    if ((i & 31) == 0) sh[i >> 5] = ss;
    __syncthreads();
    float rn = rsqrtf((sh[0] + sh[1]) * (1.0f / 128.0f) + 1.1920929e-07f);

    if (h < HQ_) {
        rn *= 0.08838834764831845f;   // fold 1/sqrt(128) into Q
        __half2* dst = (__half2*)(Qo + ((size_t)(b * HQ_ + h) * T_ + t) * DH_);
        dst[i] = __floats2half2_rn(y0 * rn, y1 * rn);
    } else {
        __half2* dst = (__half2*)(Ko + ((size_t)(b * HKV_ + (h - HQ_)) * T_ + t) * DH_);
        dst[i] = __floats2half2_rn(y0 * rn, y1 * rn);
    }
}

// ============================================================================
// Sliding-window flash attention, fp16 wmma S and PV, fp32 accumulate.
// Tile 64q x 64k, DH=128, 256 threads = 8 warps.  (unchanged from R8)
// ============================================================================
#define QL_ 136             // half ld for Q/K/V tiles (128 + 8)
#define PL_ 72              // half ld for P tile (64 + 8)
#define OL_ 132             // float ld for S/O staging (128 + 4)
#define ATTN_SMEM (64 * OL_ * (int)sizeof(float) + \
                   (3 * 64 * QL_ + 64 * PL_) * (int)sizeof(__half))

__global__ __launch_bounds__(256) void attn_tc(
    const __half* __restrict__ Qg, const __half* __restrict__ Kg,
    const __half* __restrict__ Vg, __half* __restrict__ Yg)
{
    extern __shared__ __align__(16) char asm_[];
    float*  Osf = (float*)asm_;                      // 64 x 132 fp32 staging
    __half* Qsh = (__half*)(Osf + 64 * OL_);         // 64 x 136
    __half* Ksh = Qsh + 64 * QL_;                    // 64 x 136
    __half* Vsh = Ksh + 64 * QL_;                    // 64 x 136
    __half* Psh = Vsh + 64 * QL_;                    // 64 x 72

    const int tid = threadIdx.x;
    const int tx  = tid & 15;
    const int ty  = tid >> 4;
    const int wid = tid >> 5;
    const int q0  = blockIdx.x << 6;
    const int h   = blockIdx.y;
    const int b   = blockIdx.z;
    const int hk  = h >> 2;

    const __half* Qp = Qg + ((size_t)(b * HQ_ + h) * T_ + q0) * DH_;
    const __half* Kp = Kg + ((size_t)(b * HKV_ + hk) * T_) * DH_;
    const __half* Vp = Vg + ((size_t)(b * HKV_ + hk) * T_) * DH_;

    // Q tile: pure 16B copies (Q already scaled + fp16)
    for (int li = tid; li < 64 * 16; li += 256) {
        const int r  = li >> 4;
        const int c8 = (li & 15) << 3;
        *(uint4*)(Qsh + r * QL_ + c8) = *(const uint4*)(Qp + (size_t)r * DH_ + c8);
    }

    float m_i[4], l_i[4], acc[4][8];
#pragma unroll
    for (int i = 0; i < 4; i++) {
        m_i[i] = -1e30f; l_i[i] = 0.f;
#pragma unroll
        for (int j = 0; j < 8; j++) acc[i][j] = 0.f;
    }

    int lo = q0 - (WIN_ - 1); if (lo < 0) lo = 0;
    const int kt0 = lo >> 6;
    const int kt1 = q0 >> 6;

    for (int kt = kt0; kt <= kt1; ++kt) {
        const int k0 = kt << 6;

        // ---- load K, V tiles (16B copies) ----
        for (int li = tid; li < 64 * 16; li += 256) {
            const int r  = li >> 4;
            const int c8 = (li & 15) << 3;
            *(uint4*)(Ksh + r * QL_ + c8) =
                *(const uint4*)(Kp + (size_t)(k0 + r) * DH_ + c8);
            *(uint4*)(Vsh + r * QL_ + c8) =
                *(const uint4*)(Vp + (size_t)(k0 + r) * DH_ + c8);
        }
        __syncthreads();

        // ---- S = Q K^T: warp (wy, wx) does 32q x 16k, fp32 acc -> Osf ----
        {
            const int wy = wid & 1;
            const int wx = wid >> 1;
            wmma::fragment<wmma::accumulator, 16, 16, 16, float> sacc[2];
            wmma::fill_fragment(sacc[0], 0.0f);
            wmma::fill_fragment(sacc[1], 0.0f);
#pragma unroll
            for (int d = 0; d < DH_; d += 16) {
                wmma::fragment<wmma::matrix_a, 16, 16, 16, half, wmma::row_major> af[2];
                wmma::fragment<wmma::matrix_b, 16, 16, 16, half, wmma::col_major> bf;
                wmma::load_matrix_sync(af[0], Qsh + (wy * 32 + 0)  * QL_ + d, QL_);
                wmma::load_matrix_sync(af[1], Qsh + (wy * 32 + 16) * QL_ + d, QL_);
                wmma::load_matrix_sync(bf,    Ksh + (wx * 16) * QL_ + d, QL_);
                wmma::mma_sync(sacc[0], af[0], bf, sacc[0]);
                wmma::mma_sync(sacc[1], af[1], bf, sacc[1]);
            }
            wmma::store_matrix_sync(Osf + (wy * 32 + 0)  * OL_ + wx * 16, sacc[0], OL_, wmma::mem_row_major);
            wmma::store_matrix_sync(Osf + (wy * 32 + 16) * OL_ + wx * 16, sacc[1], OL_, wmma::mem_row_major);
        }
        __syncthreads();

        // ---- softmax (SIMT): mask, online m/l update, write fp16 P ----
#pragma unroll
        for (int i = 0; i < 4; i++) {
            const int qi = q0 + ty * 4 + i;
            const float* srow = Osf + (ty * 4 + i) * OL_ + (tx << 2);
            float s0 = srow[0], s1 = srow[1], s2 = srow[2], s3 = srow[3];
            const int kj = k0 + (tx << 2);
            s0 = (qi >= kj + 0 && (qi - kj - 0) < WIN_) ? s0 : -1e30f;
            s1 = (qi >= kj + 1 && (qi - kj - 1) < WIN_) ? s1 : -1e30f;
            s2 = (qi >= kj + 2 && (qi - kj - 2) < WIN_) ? s2 : -1e30f;
            s3 = (qi >= kj + 3 && (qi - kj - 3) < WIN_) ? s3 : -1e30f;
            float rmax = fmaxf(fmaxf(s0, s1), fmaxf(s2, s3));
#pragma unroll
            for (int off = 8; off; off >>= 1)
                rmax = fmaxf(rmax, __shfl_xor_sync(0xffffffffu, rmax, off));
            const float mn = fmaxf(m_i[i], rmax);

            float p0 = __expf(s0 - mn), p1 = __expf(s1 - mn);
            float p2 = __expf(s2 - mn), p3 = __expf(s3 - mn);
            float rs = p0 + p1 + p2 + p3;
#pragma unroll
            for (int off = 8; off; off >>= 1)
                rs += __shfl_xor_sync(0xffffffffu, rs, off);

            const float sc = __expf(m_i[i] - mn);
            l_i[i] = l_i[i] * sc + rs;
            m_i[i] = mn;
#pragma unroll
            for (int j = 0; j < 8; j++) acc[i][j] *= sc;

            __half2* prow = (__half2*)(Psh + (ty * 4 + i) * PL_ + (tx << 2));
            prow[0] = __floats2half2_rn(p0, p1);
            prow[1] = __floats2half2_rn(p2, p3);
        }
        __syncthreads();

        // ---- O_tile = P V: warp (wm, wn) does 32q x 32d -> Osf ----
        {
            const int wm = (wid & 1) * 32;
            const int wn = (wid >> 1) * 32;
            wmma::fragment<wmma::accumulator, 16, 16, 16, float> oacc[2][2];
#pragma unroll
            for (int i = 0; i < 2; i++)
#pragma unroll
                for (int j = 0; j < 2; j++)
                    wmma::fill_fragment(oacc[i][j], 0.0f);
#pragma unroll
            for (int k = 0; k < 64; k += 16) {
                wmma::fragment<wmma::matrix_a, 16, 16, 16, half, wmma::row_major> af[2];
                wmma::fragment<wmma::matrix_b, 16, 16, 16, half, wmma::row_major> bf[2];
                wmma::load_matrix_sync(af[0], Psh + (wm + 0)  * PL_ + k, PL_);
                wmma::load_matrix_sync(af[1], Psh + (wm + 16) * PL_ + k, PL_);
                wmma::load_matrix_sync(bf[0], Vsh + k * QL_ + wn + 0,  QL_);
                wmma::load_matrix_sync(bf[1], Vsh + k * QL_ + wn + 16, QL_);
#pragma unroll
                for (int i = 0; i < 2; i++)
#pragma unroll
                    for (int j = 0; j < 2; j++)
                        wmma::mma_sync(oacc[i][j], af[i], bf[j], oacc[i][j]);
            }
#pragma unroll
            for (int i = 0; i < 2; i++)
#pragma unroll
                for (int j = 0; j < 2; j++)
                    wmma::store_matrix_sync(
                        Osf + (wm + i * 16) * OL_ + wn + j * 16,
                        oacc[i][j], OL_, wmma::mem_row_major);
        }
        __syncthreads();

        // ---- merge staged O tile into SIMT accumulators ----
#pragma unroll
        for (int i = 0; i < 4; i++) {
            const float* orow = Osf + (ty * 4 + i) * OL_ + (tx << 3);
#pragma unroll
            for (int j = 0; j < 8; j++) acc[i][j] += orow[j];
        }
        __syncthreads();   // Osf/Ksh/Vsh rewritten next iteration
    }

    // epilogue: y = acc / l, fp16 (feeds the proj GEMM directly)
#pragma unroll
    for (int i = 0; i < 4; i++) {
        const float inv = 1.0f / l_i[i];
        const int t = q0 + ty * 4 + i;
        __half2 o[4];
#pragma unroll
        for (int j = 0; j < 4; j++)
            o[j] = __floats2half2_rn(acc[i][2 * j] * inv, acc[i][2 * j + 1] * inv);
        *(uint4*)(Yg + ((size_t)(b * T_ + t)) * C_ + h * DH_ + (tx << 3)) =
            *(uint4*)o;
    }
}

// ============================================================================
// launch
// ============================================================================
extern "C" void kernel_launch(void* const* d_in, const int* in_sizes, int n_in,
                              void* d_out, int out_size)
{
    const float* x      = (const float*)d_in[0];
    const float* w_qkv  = (const float*)d_in[1];
    const float* w_proj = (const float*)d_in[2];
    float* out = (float*)d_out;

    float *p_qkv;
    __half *p_Qh, *p_Kh, *p_Vh, *p_yh, *p_xh, *p_wqh, *p_wph;
    cudaGetSymbolAddress((void**)&p_qkv, g_qkv);
    cudaGetSymbolAddress((void**)&p_Qh,  g_Qh);
    cudaGetSymbolAddress((void**)&p_Kh,  g_Kh);
    cudaGetSymbolAddress((void**)&p_Vh,  g_Vh);
    cudaGetSymbolAddress((void**)&p_yh,  g_yh);
    cudaGetSymbolAddress((void**)&p_xh,  g_xh);
    cudaGetSymbolAddress((void**)&p_wqh, g_wqh);
    cudaGetSymbolAddress((void**)&p_wph, g_wph);

    cudaFuncSetAttribute(gemm_fp16, cudaFuncAttributeMaxDynamicSharedMemorySize, GEMM_SMEM);
    cudaFuncSetAttribute(attn_tc, cudaFuncAttributeMaxDynamicSharedMemorySize, ATTN_SMEM);

    // 0) convert GEMM inputs to fp16 (RNE)
    to_half<<<(MTOK_ * C_ / 4 + 255) / 256, 256>>>(x, p_xh, MTOK_ * C_ / 4);
    to_half<<<(NQKV_ * C_ / 4 + 255) / 256, 256>>>(w_qkv, p_wqh, NQKV_ * C_ / 4);
    to_half<<<(C_ * C_ / 4 + 255) / 256, 256>>>(w_proj, p_wph, C_ * C_ / 4);

    // 1) qkv = x @ w_qkv^T   (fp16 HMMA, fp32 accum, 2 CTAs/SM)
    gemm_fp16<<<dim3(NQKV_ / BN_, MTOK_ / BM_), 256, GEMM_SMEM>>>(
        p_xh, p_wqh, p_qkv, MTOK_, NQKV_, C_);

    // 2) RoPE + RMSNorm + split; Q/K/V emitted fp16 (Q pre-scaled)
    rope_rms<<<dim3(HQ_ + 2 * HKV_, T_, B_), 64>>>(p_qkv, p_Qh, p_Kh, p_Vh);

    // 3) attention (fp16 tensor cores); y written fp16
    attn_tc<<<dim3(T_ / 64, HQ_, B_), 256, ATTN_SMEM>>>(p_Qh, p_Kh, p_Vh, p_yh);

    // 4) out = y @ w_proj^T  (fp16 HMMA, fp32 accum, 2 CTAs/SM)
    gemm_fp16<<<dim3(C_ / BN_, MTOK_ / BM_), 256, GEMM_SMEM>>>(
        p_yh, p_wph, out, MTOK_, C_, C_);
}